// round 1
// baseline (speedup 1.0000x reference)
#include <cuda_runtime.h>
#include <cstdint>

#define N_ATOMS 50000
#define N_PAIRS 1600000
#define FDIM 128
#define LN2F 0.6931471805599453f

// Scratch (static device allocations are allowed; cudaMalloc is not)
__device__ float g_x[(size_t)N_ATOMS * FDIM];    // atom features after input projection
__device__ float g_acc[(size_t)N_ATOMS * FDIM];  // segment-sum accumulator

// ---------------------------------------------------------------------------
// tf32 helpers
// ---------------------------------------------------------------------------
__device__ __forceinline__ uint32_t f2tf32(float x) {
    uint32_t u;
    asm("cvt.rna.tf32.f32 %0, %1;" : "=r"(u) : "f"(x));
    return u;
}

__device__ __forceinline__ void mma8(float c[4], const uint32_t a[4], const uint32_t b[2]) {
    asm volatile(
        "mma.sync.aligned.m16n8k8.row.col.f32.tf32.tf32.f32 "
        "{%0,%1,%2,%3}, {%4,%5,%6,%7}, {%8,%9}, {%0,%1,%2,%3};\n"
        : "+f"(c[0]), "+f"(c[1]), "+f"(c[2]), "+f"(c[3])
        : "r"(a[0]), "r"(a[1]), "r"(a[2]), "r"(a[3]), "r"(b[0]), "r"(b[1]));
}

__device__ __forceinline__ void red_add_v2(float* p, float x, float y) {
    asm volatile("red.global.add.v2.f32 [%0], {%1, %2};"
                 :: "l"(p), "f"(x), "f"(y) : "memory");
}

__device__ __forceinline__ float ssp(float x) {
    // shifted softplus: log1p(exp(x)) - ln2, with overflow guard
    float sp = (x > 20.f) ? x : log1pf(__expf(x));
    return sp - LN2F;
}

// ---------------------------------------------------------------------------
// 128x128 tile GEMM: C[128,128] += As[128,K] * Bs[K,128]
// 8 warps in a 4(m) x 2(n) grid; warp tile = 32(m) x 64(n); mma m16n8k8 tf32.
// ASTRIDE % 32 == 4 and BSTRIDE % 32 == 8 give conflict-free fragment loads.
// ---------------------------------------------------------------------------
template <int KSTEPS, int ASTRIDE, int BSTRIDE>
__device__ __forceinline__ void gemm128(const float* __restrict__ As,
                                        const float* __restrict__ Bs,
                                        float C[2][8][4]) {
    const int lane = threadIdx.x & 31;
    const int warp = threadIdx.x >> 5;
    const int wm = (warp >> 1) * 32;
    const int wn = (warp & 1) * 64;
    const int gid = lane >> 2;
    const int tig = lane & 3;
#pragma unroll
    for (int k = 0; k < KSTEPS; ++k) {
        uint32_t a[2][4];
#pragma unroll
        for (int i = 0; i < 2; ++i) {
            const float* ap = As + (wm + i * 16 + gid) * ASTRIDE + k * 8 + tig;
            a[i][0] = f2tf32(ap[0]);
            a[i][1] = f2tf32(ap[8 * ASTRIDE]);
            a[i][2] = f2tf32(ap[4]);
            a[i][3] = f2tf32(ap[8 * ASTRIDE + 4]);
        }
        uint32_t b[8][2];
#pragma unroll
        for (int j = 0; j < 8; ++j) {
            const float* bp = Bs + (k * 8 + tig) * BSTRIDE + wn + j * 8 + gid;
            b[j][0] = f2tf32(bp[0]);
            b[j][1] = f2tf32(bp[4 * BSTRIDE]);
        }
#pragma unroll
        for (int i = 0; i < 2; ++i)
#pragma unroll
            for (int j = 0; j < 8; ++j)
                mma8(C[i][j], a[i], b[j]);
    }
}

// ---------------------------------------------------------------------------
// Kernel: zero the accumulator (graph replays must start clean every time)
// ---------------------------------------------------------------------------
__global__ void k_zero() {
    size_t i = (size_t)blockIdx.x * blockDim.x + threadIdx.x;
    const size_t n = (size_t)N_ATOMS * FDIM / 4;
    if (i < n) reinterpret_cast<float4*>(g_acc)[i] = make_float4(0.f, 0.f, 0.f, 0.f);
}

// ---------------------------------------------------------------------------
// Kernel: x = atomic_embedding @ W_in   -> g_x
// ---------------------------------------------------------------------------
__global__ __launch_bounds__(256, 1) void k_proj(const float* __restrict__ emb,
                                                 const float* __restrict__ W_in) {
    extern __shared__ float smem[];
    float* As = smem;             // [128][132]
    float* Bs = smem + 128 * 132; // [128][136]
    const int tid = threadIdx.x;
    const int r0 = blockIdx.x * 128;

    for (int t = tid; t < 128 * 132; t += 256) {
        int r = t / 132, c = t % 132;
        float v = 0.f;
        if (c < 128 && (r0 + r) < N_ATOMS) v = emb[(size_t)(r0 + r) * 128 + c];
        As[t] = v;
    }
    for (int t = tid; t < 128 * 136; t += 256) {
        int r = t / 136, c = t % 136;
        Bs[t] = (c < 128) ? W_in[r * 128 + c] : 0.f;
    }
    __syncthreads();

    float C[2][8][4] = {};
    gemm128<16, 132, 136>(As, Bs, C);

    const int lane = threadIdx.x & 31, warp = threadIdx.x >> 5;
    const int wm = (warp >> 1) * 32, wn = (warp & 1) * 64;
    const int gid = lane >> 2, tig = lane & 3;
#pragma unroll
    for (int i = 0; i < 2; ++i) {
#pragma unroll
        for (int h = 0; h < 2; ++h) {
            int row = r0 + wm + i * 16 + gid + h * 8;
            if (row < N_ATOMS) {
#pragma unroll
                for (int j = 0; j < 8; ++j) {
                    int col = wn + j * 8 + 2 * tig;
                    float2 v = make_float2(C[i][j][h * 2 + 0], C[i][j][h * 2 + 1]);
                    *reinterpret_cast<float2*>(&g_x[(size_t)row * 128 + col]) = v;
                }
            }
        }
    }
}

// ---------------------------------------------------------------------------
// Main fused pair kernel: filter network + gather + multiply + scatter-add
// 128 pairs per CTA.
// ---------------------------------------------------------------------------
__global__ __launch_bounds__(256, 1) void k_pair(const int* __restrict__ pidx,
                                                 const float* __restrict__ f_ij,
                                                 const float* __restrict__ cut,
                                                 const float* __restrict__ W_f1,
                                                 const float* __restrict__ b_f1,
                                                 const float* __restrict__ W_f2,
                                                 const float* __restrict__ b_f2) {
    extern __shared__ float smem[];
    float* As1 = smem;                  // [128][36]  f_ij tile, K padded 20->32
    float* Bs1 = As1 + 128 * 36;        // [32][136]  W_f1 padded
    float* As2 = Bs1 + 32 * 136;        // [128][132] hidden
    float* Bs2 = As2 + 128 * 132;       // [128][136] W_f2
    float* sb1 = Bs2 + 128 * 136;       // [128]
    float* sb2 = sb1 + 128;             // [128]
    float* scut = sb2 + 128;            // [128]
    int* sidx = (int*)(scut + 128);     // [2][128] : i then j

    const int tid = threadIdx.x;
    const int p0 = blockIdx.x * 128;

    for (int t = tid; t < 128 * 36; t += 256) {
        int r = t / 36, c = t % 36;
        As1[t] = (c < 20) ? f_ij[(size_t)(p0 + r) * 20 + c] : 0.f;
    }
    for (int t = tid; t < 32 * 136; t += 256) {
        int r = t / 136, c = t % 136;
        Bs1[t] = (r < 20 && c < 128) ? W_f1[r * 128 + c] : 0.f;
    }
    for (int t = tid; t < 128 * 136; t += 256) {
        int r = t / 136, c = t % 136;
        Bs2[t] = (c < 128) ? W_f2[r * 128 + c] : 0.f;
    }
    if (tid < 128) {
        sb1[tid] = b_f1[tid];
        sb2[tid] = b_f2[tid];
        scut[tid] = cut[p0 + tid];
        sidx[tid] = pidx[p0 + tid];
        sidx[128 + tid] = pidx[N_PAIRS + p0 + tid];
    }
    __syncthreads();

    // GEMM1: hidden = ssp(f @ W_f1 + b_f1)
    float C[2][8][4] = {};
    gemm128<4, 36, 136>(As1, Bs1, C);

    const int lane = threadIdx.x & 31, warp = threadIdx.x >> 5;
    const int wm = (warp >> 1) * 32, wn = (warp & 1) * 64;
    const int gid = lane >> 2, tig = lane & 3;
#pragma unroll
    for (int i = 0; i < 2; ++i) {
        int r = wm + i * 16 + gid;
#pragma unroll
        for (int j = 0; j < 8; ++j) {
            int col = wn + j * 8 + 2 * tig;
            As2[r * 132 + col]           = ssp(C[i][j][0] + sb1[col]);
            As2[r * 132 + col + 1]       = ssp(C[i][j][1] + sb1[col + 1]);
            As2[(r + 8) * 132 + col]     = ssp(C[i][j][2] + sb1[col]);
            As2[(r + 8) * 132 + col + 1] = ssp(C[i][j][3] + sb1[col + 1]);
        }
    }
    __syncthreads();

    // GEMM2: W_ij = hidden @ W_f2 + b_f2
    float C2[2][8][4] = {};
    gemm128<16, 132, 136>(As2, Bs2, C2);

    // Epilogue: w = (W_ij + b) * cutoff; gather x[idx_j]; scatter-add to acc[idx_i]
#pragma unroll
    for (int i = 0; i < 2; ++i) {
#pragma unroll
        for (int h = 0; h < 2; ++h) {
            int r = wm + i * 16 + gid + h * 8;
            int ai = sidx[r];
            int aj = sidx[128 + r];
            float ct = scut[r];
            const float* xrow = g_x + (size_t)aj * 128;
            float* arow = g_acc + (size_t)ai * 128;
#pragma unroll
            for (int j = 0; j < 8; ++j) {
                int col = wn + j * 8 + 2 * tig;
                float w0 = (C2[i][j][h * 2 + 0] + sb2[col]) * ct;
                float w1 = (C2[i][j][h * 2 + 1] + sb2[col + 1]) * ct;
                float2 xv = *reinterpret_cast<const float2*>(xrow + col);
                red_add_v2(arow + col, w0 * xv.x, w1 * xv.y);
            }
        }
    }
}

// ---------------------------------------------------------------------------
// Output MLP: out = ssp(acc @ W_o1 + b_o1) @ W_o2 + b_o2
// ---------------------------------------------------------------------------
__global__ __launch_bounds__(256, 1) void k_out(const float* __restrict__ W_o1,
                                                const float* __restrict__ b_o1,
                                                const float* __restrict__ W_o2,
                                                const float* __restrict__ b_o2,
                                                float* __restrict__ out) {
    extern __shared__ float smem[];
    float* As = smem;             // [128][132]
    float* Bs = smem + 128 * 132; // [128][136]
    float* sb = Bs + 128 * 136;   // [128]
    const int tid = threadIdx.x;
    const int r0 = blockIdx.x * 128;

    for (int t = tid; t < 128 * 132; t += 256) {
        int r = t / 132, c = t % 132;
        float v = 0.f;
        if (c < 128 && (r0 + r) < N_ATOMS) v = g_acc[(size_t)(r0 + r) * 128 + c];
        As[t] = v;
    }
    for (int t = tid; t < 128 * 136; t += 256) {
        int r = t / 136, c = t % 136;
        Bs[t] = (c < 128) ? W_o1[r * 128 + c] : 0.f;
    }
    if (tid < 128) sb[tid] = b_o1[tid];
    __syncthreads();

    float C[2][8][4] = {};
    gemm128<16, 132, 136>(As, Bs, C);
    __syncthreads();  // all warps done reading As before we overwrite it

    const int lane = threadIdx.x & 31, warp = threadIdx.x >> 5;
    const int wm = (warp >> 1) * 32, wn = (warp & 1) * 64;
    const int gid = lane >> 2, tig = lane & 3;
#pragma unroll
    for (int i = 0; i < 2; ++i) {
        int r = wm + i * 16 + gid;
#pragma unroll
        for (int j = 0; j < 8; ++j) {
            int col = wn + j * 8 + 2 * tig;
            As[r * 132 + col]           = ssp(C[i][j][0] + sb[col]);
            As[r * 132 + col + 1]       = ssp(C[i][j][1] + sb[col + 1]);
            As[(r + 8) * 132 + col]     = ssp(C[i][j][2] + sb[col]);
            As[(r + 8) * 132 + col + 1] = ssp(C[i][j][3] + sb[col + 1]);
        }
    }
    for (int t = tid; t < 128 * 136; t += 256) {
        int r = t / 136, c = t % 136;
        Bs[t] = (c < 128) ? W_o2[r * 128 + c] : 0.f;
    }
    if (tid < 128) sb[tid] = b_o2[tid];
    __syncthreads();

    float C2[2][8][4] = {};
    gemm128<16, 132, 136>(As, Bs, C2);

#pragma unroll
    for (int i = 0; i < 2; ++i) {
#pragma unroll
        for (int h = 0; h < 2; ++h) {
            int row = r0 + wm + i * 16 + gid + h * 8;
            if (row < N_ATOMS) {
#pragma unroll
                for (int j = 0; j < 8; ++j) {
                    int col = wn + j * 8 + 2 * tig;
                    float2 v = make_float2(C2[i][j][h * 2 + 0] + sb[col],
                                           C2[i][j][h * 2 + 1] + sb[col + 1]);
                    *reinterpret_cast<float2*>(&out[(size_t)row * 128 + col]) = v;
                }
            }
        }
    }
}

// ---------------------------------------------------------------------------
// Launch
// ---------------------------------------------------------------------------
extern "C" void kernel_launch(void* const* d_in, const int* in_sizes, int n_in,
                              void* d_out, int out_size) {
    const float* emb  = (const float*)d_in[0];
    const int*   pidx = (const int*)d_in[1];
    const float* fij  = (const float*)d_in[2];
    const float* cut  = (const float*)d_in[3];
    const float* W_in = (const float*)d_in[4];
    const float* W_f1 = (const float*)d_in[5];
    const float* b_f1 = (const float*)d_in[6];
    const float* W_f2 = (const float*)d_in[7];
    const float* b_f2 = (const float*)d_in[8];
    const float* W_o1 = (const float*)d_in[9];
    const float* b_o1 = (const float*)d_in[10];
    const float* W_o2 = (const float*)d_in[11];
    const float* b_o2 = (const float*)d_in[12];
    float* out = (float*)d_out;

    const int smemPair = (128 * 36 + 32 * 136 + 128 * 132 + 128 * 136 + 3 * 128 + 256) * 4;
    const int smemGemm = (128 * 132 + 128 * 136 + 128) * 4;

    cudaFuncSetAttribute(k_pair, cudaFuncAttributeMaxDynamicSharedMemorySize, smemPair);
    cudaFuncSetAttribute(k_proj, cudaFuncAttributeMaxDynamicSharedMemorySize, smemGemm);
    cudaFuncSetAttribute(k_out,  cudaFuncAttributeMaxDynamicSharedMemorySize, smemGemm);

    k_zero<<<(N_ATOMS * FDIM / 4 + 255) / 256, 256>>>();
    k_proj<<<(N_ATOMS + 127) / 128, 256, smemGemm>>>(emb, W_in);
    k_pair<<<N_PAIRS / 128, 256, smemPair>>>(pidx, fij, cut, W_f1, b_f1, W_f2, b_f2);
    k_out<<<(N_ATOMS + 127) / 128, 256, smemGemm>>>(W_o1, b_o1, W_o2, b_o2, out);
}

// round 2
// speedup vs baseline: 1.8433x; 1.8433x over previous
#include <cuda_runtime.h>
#include <cstdint>

#define N_ATOMS 50000
#define N_PAIRS 1600000
#define FDIM 128
#define LN2F 0.6931471805599453f

__device__ float g_x[(size_t)N_ATOMS * FDIM];    // atom features after input projection
__device__ float g_acc[(size_t)N_ATOMS * FDIM];  // segment-sum accumulator

// ---------------------------------------------------------------------------
// helpers
// ---------------------------------------------------------------------------
__device__ __forceinline__ uint32_t f2tf32(float x) {
    uint32_t u;
    asm("cvt.rna.tf32.f32 %0, %1;" : "=r"(u) : "f"(x));
    return u;
}
__device__ __forceinline__ float tf32f(float x) { return __uint_as_float(f2tf32(x)); }

__device__ __forceinline__ void mma8(float c[4], const uint32_t a[4], const uint32_t b[2]) {
    asm volatile(
        "mma.sync.aligned.m16n8k8.row.col.f32.tf32.tf32.f32 "
        "{%0,%1,%2,%3}, {%4,%5,%6,%7}, {%8,%9}, {%0,%1,%2,%3};\n"
        : "+f"(c[0]), "+f"(c[1]), "+f"(c[2]), "+f"(c[3])
        : "r"(a[0]), "r"(a[1]), "r"(a[2]), "r"(a[3]), "r"(b[0]), "r"(b[1]));
}

__device__ __forceinline__ void red_add_v4(float* p, float a, float b, float c, float d) {
    asm volatile("red.global.add.v4.f32 [%0], {%1, %2, %3, %4};"
                 :: "l"(p), "f"(a), "f"(b), "f"(c), "f"(d) : "memory");
}

__device__ __forceinline__ float ssp(float x) {
    float sp = (x > 20.f) ? x : log1pf(__expf(x));
    return sp - LN2F;
}

__device__ __forceinline__ void barh(int id) {
    asm volatile("bar.sync %0, 256;" :: "r"(id) : "memory");
}

// ---------------------------------------------------------------------------
// 128x128 tile GEMM on PRE-CONVERTED tf32 smem tiles.
// 8 warps (tid 0..255) in 4(m) x 2(n); warp tile 32m x 64n; mma m16n8k8.
// ---------------------------------------------------------------------------
template <int KSTEPS, int ASTRIDE, int BSTRIDE>
__device__ __forceinline__ void gemm128(const float* __restrict__ As,
                                        const float* __restrict__ Bs,
                                        float C[2][8][4], int tid) {
    const int lane = tid & 31;
    const int warp = tid >> 5;
    const int wm = (warp >> 1) * 32;
    const int wn = (warp & 1) * 64;
    const int gid = lane >> 2;
    const int tig = lane & 3;
#pragma unroll
    for (int k = 0; k < KSTEPS; ++k) {
        uint32_t a[2][4];
#pragma unroll
        for (int i = 0; i < 2; ++i) {
            const float* ap = As + (wm + i * 16 + gid) * ASTRIDE + k * 8 + tig;
            a[i][0] = __float_as_uint(ap[0]);
            a[i][1] = __float_as_uint(ap[8 * ASTRIDE]);
            a[i][2] = __float_as_uint(ap[4]);
            a[i][3] = __float_as_uint(ap[8 * ASTRIDE + 4]);
        }
        uint32_t b[8][2];
#pragma unroll
        for (int j = 0; j < 8; ++j) {
            const float* bp = Bs + (k * 8 + tig) * BSTRIDE + wn + j * 8 + gid;
            b[j][0] = __float_as_uint(bp[0]);
            b[j][1] = __float_as_uint(bp[4 * BSTRIDE]);
        }
#pragma unroll
        for (int i = 0; i < 2; ++i)
#pragma unroll
            for (int j = 0; j < 8; ++j)
                mma8(C[i][j], a[i], b[j]);
    }
}

// ---------------------------------------------------------------------------
// zero the accumulator (every replay must start clean)
// ---------------------------------------------------------------------------
__global__ void k_zero() {
    size_t i = (size_t)blockIdx.x * blockDim.x + threadIdx.x;
    const size_t n = (size_t)N_ATOMS * FDIM / 4;
    if (i < n) reinterpret_cast<float4*>(g_acc)[i] = make_float4(0.f, 0.f, 0.f, 0.f);
}

// ---------------------------------------------------------------------------
// x = atomic_embedding @ W_in -> g_x
// ---------------------------------------------------------------------------
__global__ __launch_bounds__(256, 1) void k_proj(const float* __restrict__ emb,
                                                 const float* __restrict__ W_in) {
    extern __shared__ float smem[];
    float* As = smem;             // [128][132] tf32
    float* Bs = smem + 128 * 132; // [128][136] tf32
    const int tid = threadIdx.x;
    const int r0 = blockIdx.x * 128;

    for (int t = tid; t < 128 * 132; t += 256) {
        int r = t / 132, c = t % 132;
        float v = 0.f;
        if (c < 128 && (r0 + r) < N_ATOMS) v = emb[(size_t)(r0 + r) * 128 + c];
        As[t] = tf32f(v);
    }
    for (int t = tid; t < 128 * 136; t += 256) {
        int r = t / 136, c = t % 136;
        Bs[t] = (c < 128) ? tf32f(W_in[r * 128 + c]) : 0.f;
    }
    __syncthreads();

    float C[2][8][4] = {};
    gemm128<16, 132, 136>(As, Bs, C, tid);

    const int lane = tid & 31, warp = tid >> 5;
    const int wm = (warp >> 1) * 32, wn = (warp & 1) * 64;
    const int gid = lane >> 2, tig = lane & 3;
#pragma unroll
    for (int i = 0; i < 2; ++i)
#pragma unroll
        for (int h = 0; h < 2; ++h) {
            int row = r0 + wm + i * 16 + gid + h * 8;
            if (row < N_ATOMS)
#pragma unroll
                for (int j = 0; j < 8; ++j) {
                    int col = wn + j * 8 + 2 * tig;
                    float2 v = make_float2(C[i][j][h * 2 + 0], C[i][j][h * 2 + 1]);
                    *reinterpret_cast<float2*>(&g_x[(size_t)row * 128 + col]) = v;
                }
        }
}

// ---------------------------------------------------------------------------
// Persistent fused pair kernel. 512 threads = two independent 256-thread
// halves, each working one 128-pair tile at a time; weights shared in smem.
// ---------------------------------------------------------------------------
__global__ __launch_bounds__(512, 1) void k_pair(const int* __restrict__ pidx,
                                                 const float* __restrict__ f_ij,
                                                 const float* __restrict__ cut,
                                                 const float* __restrict__ W_f1,
                                                 const float* __restrict__ b_f1,
                                                 const float* __restrict__ W_f2,
                                                 const float* __restrict__ b_f2,
                                                 int tile_base, int tile_count) {
    extern __shared__ float smem[];
    float* Bs1 = smem;                      // [32][136] tf32 W_f1 (K padded 20->32)
    float* Bs2 = Bs1 + 32 * 136;            // [128][136] tf32 W_f2
    float* sb1 = Bs2 + 128 * 136;           // [128]
    float* sb2 = sb1 + 128;                 // [128]
    // per-half region: AsH [128][132] (also hosts the [128][36] GEMM1 A tile),
    // scut[128], sidx[256]
    const int HALFSZ = 128 * 132 + 128 + 256;
    const int tid = threadIdx.x;
    const int half = tid >> 8;              // 0 or 1
    const int htid = tid & 255;
    float* AsH  = sb2 + 128 + half * HALFSZ;
    float* scut = AsH + 128 * 132;
    int*   sidx = (int*)(scut + 128);

    // --- load shared weights once (all 512 threads) ---
    for (int t = tid; t < 32 * 136; t += 512) {
        int r = t / 136, c = t % 136;
        Bs1[t] = (r < 20 && c < 128) ? tf32f(W_f1[r * 128 + c]) : 0.f;
    }
    for (int t = tid; t < 128 * 136; t += 512) {
        int r = t / 136, c = t % 136;
        Bs2[t] = (c < 128) ? tf32f(W_f2[r * 128 + c]) : 0.f;
    }
    if (tid < 128) sb1[tid] = b_f1[tid];
    else if (tid < 256) sb2[tid - 128] = b_f2[tid - 128];
    __syncthreads();

    const int bar = 1 + half;
    const int lane = htid & 31, warp = htid >> 5;
    const int wm = (warp >> 1) * 32, wn = (warp & 1) * 64;
    const int gid = lane >> 2, tig = lane & 3;

    for (int tile = tile_base + blockIdx.x * 2 + half;
         tile < tile_base + tile_count; tile += gridDim.x * 2) {
        const int p0 = tile * 128;

        // --- stage f_ij tile (tf32, K padded to 32, stride 36) + meta ---
        for (int t = htid; t < 128 * 36; t += 256) {
            int r = t / 36, c = t % 36;
            AsH[r * 36 + c] = (c < 20) ? tf32f(f_ij[(size_t)(p0 + r) * 20 + c]) : 0.f;
        }
        if (htid < 128) {
            scut[htid] = cut[p0 + htid];
            sidx[htid] = pidx[p0 + htid];
            sidx[128 + htid] = pidx[N_PAIRS + p0 + htid];
        }
        barh(bar);

        // --- GEMM1: hidden = ssp(f @ W_f1 + b_f1) ---
        float C[2][8][4] = {};
        gemm128<4, 36, 136>(AsH, Bs1, C, htid);
        barh(bar);  // all reads of the f_ij tile done before overwrite

        // write hidden as tf32 into AsH (stride 132)
#pragma unroll
        for (int i = 0; i < 2; ++i) {
            int r = wm + i * 16 + gid;
#pragma unroll
            for (int j = 0; j < 8; ++j) {
                int col = wn + j * 8 + 2 * tig;
                AsH[r * 132 + col]           = tf32f(ssp(C[i][j][0] + sb1[col]));
                AsH[r * 132 + col + 1]       = tf32f(ssp(C[i][j][1] + sb1[col + 1]));
                AsH[(r + 8) * 132 + col]     = tf32f(ssp(C[i][j][2] + sb1[col]));
                AsH[(r + 8) * 132 + col + 1] = tf32f(ssp(C[i][j][3] + sb1[col + 1]));
            }
        }
        barh(bar);

        // --- GEMM2: W_ij = hidden @ W_f2 + b_f2 ---
        float C2[2][8][4] = {};
        gemm128<16, 132, 136>(AsH, Bs2, C2, htid);
        barh(bar);  // all reads of hidden done before staging W_ij

        // stage w = (W_ij + b2) * cutoff into AsH (fp32)
#pragma unroll
        for (int i = 0; i < 2; ++i)
#pragma unroll
            for (int h = 0; h < 2; ++h) {
                int r = wm + i * 16 + gid + h * 8;
                float ct = scut[r];
#pragma unroll
                for (int j = 0; j < 8; ++j) {
                    int col = wn + j * 8 + 2 * tig;
                    float2 v = make_float2((C2[i][j][h * 2 + 0] + sb2[col]) * ct,
                                           (C2[i][j][h * 2 + 1] + sb2[col + 1]) * ct);
                    *reinterpret_cast<float2*>(&AsH[r * 132 + col]) = v;
                }
            }
        barh(bar);

        // --- epilogue: thread owns a contiguous 64-float half-row ---
        {
            int r = htid >> 1;
            int ch = (htid & 1) * 64;
            int aj = sidx[128 + r];
            int ai = sidx[r];
            const float4* xr = reinterpret_cast<const float4*>(g_x + (size_t)aj * 128 + ch);
            float* ar = g_acc + (size_t)ai * 128 + ch;
            const float* wr = AsH + r * 132 + ch;
#pragma unroll
            for (int q = 0; q < 16; ++q) {
                float4 xv = __ldg(xr + q);
                float4 wv = *reinterpret_cast<const float4*>(wr + 4 * q);
                red_add_v4(ar + 4 * q, wv.x * xv.x, wv.y * xv.y, wv.z * xv.z, wv.w * xv.w);
            }
        }
        barh(bar);  // epilogue reads AsH/sidx finished before next tile's fill
    }
}

// ---------------------------------------------------------------------------
// Output MLP: out = ssp(acc @ W_o1 + b_o1) @ W_o2 + b_o2
// ---------------------------------------------------------------------------
__global__ __launch_bounds__(256, 1) void k_out(const float* __restrict__ W_o1,
                                                const float* __restrict__ b_o1,
                                                const float* __restrict__ W_o2,
                                                const float* __restrict__ b_o2,
                                                float* __restrict__ out) {
    extern __shared__ float smem[];
    float* As = smem;             // [128][132]
    float* Bs = smem + 128 * 132; // [128][136]
    float* sb = Bs + 128 * 136;   // [128]
    const int tid = threadIdx.x;
    const int r0 = blockIdx.x * 128;

    for (int t = tid; t < 128 * 132; t += 256) {
        int r = t / 132, c = t % 132;
        float v = 0.f;
        if (c < 128 && (r0 + r) < N_ATOMS) v = g_acc[(size_t)(r0 + r) * 128 + c];
        As[t] = tf32f(v);
    }
    for (int t = tid; t < 128 * 136; t += 256) {
        int r = t / 136, c = t % 136;
        Bs[t] = (c < 128) ? tf32f(W_o1[r * 128 + c]) : 0.f;
    }
    if (tid < 128) sb[tid] = b_o1[tid];
    __syncthreads();

    float C[2][8][4] = {};
    gemm128<16, 132, 136>(As, Bs, C, tid);
    __syncthreads();

    const int lane = tid & 31, warp = tid >> 5;
    const int wm = (warp >> 1) * 32, wn = (warp & 1) * 64;
    const int gid = lane >> 2, tig = lane & 3;
#pragma unroll
    for (int i = 0; i < 2; ++i) {
        int r = wm + i * 16 + gid;
#pragma unroll
        for (int j = 0; j < 8; ++j) {
            int col = wn + j * 8 + 2 * tig;
            As[r * 132 + col]           = tf32f(ssp(C[i][j][0] + sb[col]));
            As[r * 132 + col + 1]       = tf32f(ssp(C[i][j][1] + sb[col + 1]));
            As[(r + 8) * 132 + col]     = tf32f(ssp(C[i][j][2] + sb[col]));
            As[(r + 8) * 132 + col + 1] = tf32f(ssp(C[i][j][3] + sb[col + 1]));
        }
    }
    for (int t = tid; t < 128 * 136; t += 256) {
        int r = t / 136, c = t % 136;
        Bs[t] = (c < 128) ? tf32f(W_o2[r * 128 + c]) : 0.f;
    }
    if (tid < 128) sb[tid] = b_o2[tid];
    __syncthreads();

    float C2[2][8][4] = {};
    gemm128<16, 132, 136>(As, Bs, C2, tid);

#pragma unroll
    for (int i = 0; i < 2; ++i)
#pragma unroll
        for (int h = 0; h < 2; ++h) {
            int row = r0 + wm + i * 16 + gid + h * 8;
            if (row < N_ATOMS)
#pragma unroll
                for (int j = 0; j < 8; ++j) {
                    int col = wn + j * 8 + 2 * tig;
                    float2 v = make_float2(C2[i][j][h * 2 + 0] + sb[col],
                                           C2[i][j][h * 2 + 1] + sb[col + 1]);
                    *reinterpret_cast<float2*>(&out[(size_t)row * 128 + col]) = v;
                }
        }
}

// ---------------------------------------------------------------------------
// Launch
// ---------------------------------------------------------------------------
extern "C" void kernel_launch(void* const* d_in, const int* in_sizes, int n_in,
                              void* d_out, int out_size) {
    const float* emb  = (const float*)d_in[0];
    const int*   pidx = (const int*)d_in[1];
    const float* fij  = (const float*)d_in[2];
    const float* cut  = (const float*)d_in[3];
    const float* W_in = (const float*)d_in[4];
    const float* W_f1 = (const float*)d_in[5];
    const float* b_f1 = (const float*)d_in[6];
    const float* W_f2 = (const float*)d_in[7];
    const float* b_f2 = (const float*)d_in[8];
    const float* W_o1 = (const float*)d_in[9];
    const float* b_o1 = (const float*)d_in[10];
    const float* W_o2 = (const float*)d_in[11];
    const float* b_o2 = (const float*)d_in[12];
    float* out = (float*)d_out;

    const int HALFSZ = 128 * 132 + 128 + 256;
    const int smemPair = (32 * 136 + 128 * 136 + 256 + 2 * HALFSZ) * 4;  // 226304 B
    const int smemGemm = (128 * 132 + 128 * 136 + 128) * 4;

    cudaFuncSetAttribute(k_pair, cudaFuncAttributeMaxDynamicSharedMemorySize, smemPair);
    cudaFuncSetAttribute(k_proj, cudaFuncAttributeMaxDynamicSharedMemorySize, smemGemm);
    cudaFuncSetAttribute(k_out,  cudaFuncAttributeMaxDynamicSharedMemorySize, smemGemm);

    const int NTILES = N_PAIRS / 128;  // 12500
    k_zero<<<(N_ATOMS * FDIM / 4 + 255) / 256, 256>>>();
    k_proj<<<(N_ATOMS + 127) / 128, 256, smemGemm>>>(emb, W_in);
    k_pair<<<148, 512, smemPair>>>(pidx, fij, cut, W_f1, b_f1, W_f2, b_f2, 0, NTILES / 2);
    k_pair<<<148, 512, smemPair>>>(pidx, fij, cut, W_f1, b_f1, W_f2, b_f2, NTILES / 2, NTILES - NTILES / 2);
    k_out<<<(N_ATOMS + 127) / 128, 256, smemGemm>>>(W_o1, b_o1, W_o2, b_o2, out);
}

// round 3
// speedup vs baseline: 1.8623x; 1.0103x over previous
#include <cuda_runtime.h>
#include <cstdint>

#define N_ATOMS 50000
#define N_PAIRS 1600000
#define FDIM 128
#define LN2F 0.6931471805599453f

__device__ float g_x[(size_t)N_ATOMS * FDIM];    // atom features after input projection
__device__ float g_acc[(size_t)N_ATOMS * FDIM];  // segment-sum accumulator

// ---------------------------------------------------------------------------
// helpers
// ---------------------------------------------------------------------------
__device__ __forceinline__ uint32_t f2tf32(float x) {
    uint32_t u;
    asm("cvt.rna.tf32.f32 %0, %1;" : "=r"(u) : "f"(x));
    return u;
}
__device__ __forceinline__ float tf32f(float x) { return __uint_as_float(f2tf32(x)); }

__device__ __forceinline__ void mma8(float c[4], const uint32_t a[4], const uint32_t b[2]) {
    asm volatile(
        "mma.sync.aligned.m16n8k8.row.col.f32.tf32.tf32.f32 "
        "{%0,%1,%2,%3}, {%4,%5,%6,%7}, {%8,%9}, {%0,%1,%2,%3};\n"
        : "+f"(c[0]), "+f"(c[1]), "+f"(c[2]), "+f"(c[3])
        : "r"(a[0]), "r"(a[1]), "r"(a[2]), "r"(a[3]), "r"(b[0]), "r"(b[1]));
}

__device__ __forceinline__ void red_add_v4(float* p, float a, float b, float c, float d) {
    asm volatile("red.global.add.v4.f32 [%0], {%1, %2, %3, %4};"
                 :: "l"(p), "f"(a), "f"(b), "f"(c), "f"(d) : "memory");
}

__device__ __forceinline__ float ssp(float x) {
    float sp = (x > 20.f) ? x : log1pf(__expf(x));
    return sp - LN2F;
}

__device__ __forceinline__ void barh(int id) {
    asm volatile("bar.sync %0, 256;" :: "r"(id) : "memory");
}

// ---------------------------------------------------------------------------
// 128x128 tile GEMM on PRE-CONVERTED tf32 smem tiles.
// 8 warps (tid 0..255) in 4(m) x 2(n); warp tile 32m x 64n; mma m16n8k8.
// ---------------------------------------------------------------------------
template <int KSTEPS, int ASTRIDE, int BSTRIDE>
__device__ __forceinline__ void gemm128(const float* __restrict__ As,
                                        const float* __restrict__ Bs,
                                        float C[2][8][4], int tid) {
    const int lane = tid & 31;
    const int warp = tid >> 5;
    const int wm = (warp >> 1) * 32;
    const int wn = (warp & 1) * 64;
    const int gid = lane >> 2;
    const int tig = lane & 3;
#pragma unroll
    for (int k = 0; k < KSTEPS; ++k) {
        uint32_t a[2][4];
#pragma unroll
        for (int i = 0; i < 2; ++i) {
            const float* ap = As + (wm + i * 16 + gid) * ASTRIDE + k * 8 + tig;
            a[i][0] = __float_as_uint(ap[0]);
            a[i][1] = __float_as_uint(ap[8 * ASTRIDE]);
            a[i][2] = __float_as_uint(ap[4]);
            a[i][3] = __float_as_uint(ap[8 * ASTRIDE + 4]);
        }
        uint32_t b[8][2];
#pragma unroll
        for (int j = 0; j < 8; ++j) {
            const float* bp = Bs + (k * 8 + tig) * BSTRIDE + wn + j * 8 + gid;
            b[j][0] = __float_as_uint(bp[0]);
            b[j][1] = __float_as_uint(bp[4 * BSTRIDE]);
        }
#pragma unroll
        for (int i = 0; i < 2; ++i)
#pragma unroll
            for (int j = 0; j < 8; ++j)
                mma8(C[i][j], a[i], b[j]);
    }
}

// ---------------------------------------------------------------------------
// zero the accumulator (every replay must start clean)
// ---------------------------------------------------------------------------
__global__ void k_zero() {
    size_t i = (size_t)blockIdx.x * blockDim.x + threadIdx.x;
    const size_t n = (size_t)N_ATOMS * FDIM / 4;
    if (i < n) reinterpret_cast<float4*>(g_acc)[i] = make_float4(0.f, 0.f, 0.f, 0.f);
}

// ---------------------------------------------------------------------------
// x = atomic_embedding @ W_in -> g_x
// ---------------------------------------------------------------------------
__global__ __launch_bounds__(256, 1) void k_proj(const float* __restrict__ emb,
                                                 const float* __restrict__ W_in) {
    extern __shared__ float smem[];
    float* As = smem;             // [128][132] tf32
    float* Bs = smem + 128 * 132; // [128][136] tf32
    const int tid = threadIdx.x;
    const int r0 = blockIdx.x * 128;

    for (int t = tid; t < 128 * 132; t += 256) {
        int r = t / 132, c = t % 132;
        float v = 0.f;
        if (c < 128 && (r0 + r) < N_ATOMS) v = emb[(size_t)(r0 + r) * 128 + c];
        As[t] = tf32f(v);
    }
    for (int t = tid; t < 128 * 136; t += 256) {
        int r = t / 136, c = t % 136;
        Bs[t] = (c < 128) ? tf32f(W_in[r * 128 + c]) : 0.f;
    }
    __syncthreads();

    float C[2][8][4] = {};
    gemm128<16, 132, 136>(As, Bs, C, tid);

    const int lane = tid & 31, warp = tid >> 5;
    const int wm = (warp >> 1) * 32, wn = (warp & 1) * 64;
    const int gid = lane >> 2, tig = lane & 3;
#pragma unroll
    for (int i = 0; i < 2; ++i)
#pragma unroll
        for (int h = 0; h < 2; ++h) {
            int row = r0 + wm + i * 16 + gid + h * 8;
            if (row < N_ATOMS)
#pragma unroll
                for (int j = 0; j < 8; ++j) {
                    int col = wn + j * 8 + 2 * tig;
                    float2 v = make_float2(C[i][j][h * 2 + 0], C[i][j][h * 2 + 1]);
                    *reinterpret_cast<float2*>(&g_x[(size_t)row * 128 + col]) = v;
                }
        }
}

// ---------------------------------------------------------------------------
// Persistent fused pair kernel. 512 threads = two independent 256-thread
// halves, each working one 128-pair tile at a time; weights shared in smem.
// ---------------------------------------------------------------------------
__global__ __launch_bounds__(512, 1) void k_pair(const int* __restrict__ pidx,
                                                 const float* __restrict__ f_ij,
                                                 const float* __restrict__ cut,
                                                 const float* __restrict__ W_f1,
                                                 const float* __restrict__ b_f1,
                                                 const float* __restrict__ W_f2,
                                                 const float* __restrict__ b_f2,
                                                 int tile_base, int tile_count) {
    extern __shared__ float smem[];
    float* Bs1 = smem;                      // [32][136] tf32 W_f1 (K padded 20->32)
    float* Bs2 = Bs1 + 32 * 136;            // [128][136] tf32 W_f2
    float* sb1 = Bs2 + 128 * 136;           // [128]
    float* sb2 = sb1 + 128;                 // [128]
    // per-half region: AsH [128][132] (also hosts the [128][36] GEMM1 A tile),
    // scut[128], sidx[256]
    const int HALFSZ = 128 * 132 + 128 + 256;
    const int tid = threadIdx.x;
    const int half = tid >> 8;              // 0 or 1
    const int htid = tid & 255;
    float* AsH  = sb2 + 128 + half * HALFSZ;
    float* scut = AsH + 128 * 132;
    int*   sidx = (int*)(scut + 128);

    // --- load shared weights once (all 512 threads) ---
    for (int t = tid; t < 32 * 136; t += 512) {
        int r = t / 136, c = t % 136;
        Bs1[t] = (r < 20 && c < 128) ? tf32f(W_f1[r * 128 + c]) : 0.f;
    }
    for (int t = tid; t < 128 * 136; t += 512) {
        int r = t / 136, c = t % 136;
        Bs2[t] = (c < 128) ? tf32f(W_f2[r * 128 + c]) : 0.f;
    }
    if (tid < 128) sb1[tid] = b_f1[tid];
    else if (tid < 256) sb2[tid - 128] = b_f2[tid - 128];
    __syncthreads();

    const int bar = 1 + half;
    const int lane = htid & 31, warp = htid >> 5;
    const int wm = (warp >> 1) * 32, wn = (warp & 1) * 64;
    const int gid = lane >> 2, tig = lane & 3;

    for (int tile = tile_base + blockIdx.x * 2 + half;
         tile < tile_base + tile_count; tile += gridDim.x * 2) {
        const int p0 = tile * 128;

        // --- stage f_ij tile (tf32, K padded to 32, stride 36) + meta ---
        for (int t = htid; t < 128 * 36; t += 256) {
            int r = t / 36, c = t % 36;
            AsH[r * 36 + c] = (c < 20) ? tf32f(f_ij[(size_t)(p0 + r) * 20 + c]) : 0.f;
        }
        if (htid < 128) {
            scut[htid] = cut[p0 + htid];
            sidx[htid] = pidx[p0 + htid];
            sidx[128 + htid] = pidx[N_PAIRS + p0 + htid];
        }
        barh(bar);

        // --- GEMM1: hidden = ssp(f @ W_f1 + b_f1) ---
        float C[2][8][4] = {};
        gemm128<4, 36, 136>(AsH, Bs1, C, htid);
        barh(bar);  // all reads of the f_ij tile done before overwrite

        // write hidden as tf32 into AsH (stride 132)
#pragma unroll
        for (int i = 0; i < 2; ++i) {
            int r = wm + i * 16 + gid;
#pragma unroll
            for (int j = 0; j < 8; ++j) {
                int col = wn + j * 8 + 2 * tig;
                AsH[r * 132 + col]           = tf32f(ssp(C[i][j][0] + sb1[col]));
                AsH[r * 132 + col + 1]       = tf32f(ssp(C[i][j][1] + sb1[col + 1]));
                AsH[(r + 8) * 132 + col]     = tf32f(ssp(C[i][j][2] + sb1[col]));
                AsH[(r + 8) * 132 + col + 1] = tf32f(ssp(C[i][j][3] + sb1[col + 1]));
            }
        }
        barh(bar);

        // --- GEMM2: W_ij = hidden @ W_f2 + b_f2 ---
        float C2[2][8][4] = {};
        gemm128<16, 132, 136>(AsH, Bs2, C2, htid);
        barh(bar);  // all reads of hidden done before staging W_ij

        // stage w = (W_ij + b2) * cutoff into AsH (fp32)
#pragma unroll
        for (int i = 0; i < 2; ++i)
#pragma unroll
            for (int h = 0; h < 2; ++h) {
                int r = wm + i * 16 + gid + h * 8;
                float ct = scut[r];
#pragma unroll
                for (int j = 0; j < 8; ++j) {
                    int col = wn + j * 8 + 2 * tig;
                    float2 v = make_float2((C2[i][j][h * 2 + 0] + sb2[col]) * ct,
                                           (C2[i][j][h * 2 + 1] + sb2[col + 1]) * ct);
                    *reinterpret_cast<float2*>(&AsH[r * 132 + col]) = v;
                }
            }
        barh(bar);

        // --- epilogue: thread owns a contiguous 64-float half-row ---
        {
            int r = htid >> 1;
            int ch = (htid & 1) * 64;
            int aj = sidx[128 + r];
            int ai = sidx[r];
            const float4* xr = reinterpret_cast<const float4*>(g_x + (size_t)aj * 128 + ch);
            float* ar = g_acc + (size_t)ai * 128 + ch;
            const float* wr = AsH + r * 132 + ch;
#pragma unroll
            for (int q = 0; q < 16; ++q) {
                float4 xv = __ldg(xr + q);
                float4 wv = *reinterpret_cast<const float4*>(wr + 4 * q);
                red_add_v4(ar + 4 * q, wv.x * xv.x, wv.y * xv.y, wv.z * xv.z, wv.w * xv.w);
            }
        }
        barh(bar);  // epilogue reads AsH/sidx finished before next tile's fill
    }
}

// ---------------------------------------------------------------------------
// Output MLP: out = ssp(acc @ W_o1 + b_o1) @ W_o2 + b_o2
// ---------------------------------------------------------------------------
__global__ __launch_bounds__(256, 1) void k_out(const float* __restrict__ W_o1,
                                                const float* __restrict__ b_o1,
                                                const float* __restrict__ W_o2,
                                                const float* __restrict__ b_o2,
                                                float* __restrict__ out) {
    extern __shared__ float smem[];
    float* As = smem;             // [128][132]
    float* Bs = smem + 128 * 132; // [128][136]
    float* sb = Bs + 128 * 136;   // [128]
    const int tid = threadIdx.x;
    const int r0 = blockIdx.x * 128;

    for (int t = tid; t < 128 * 132; t += 256) {
        int r = t / 132, c = t % 132;
        float v = 0.f;
        if (c < 128 && (r0 + r) < N_ATOMS) v = g_acc[(size_t)(r0 + r) * 128 + c];
        As[t] = tf32f(v);
    }
    for (int t = tid; t < 128 * 136; t += 256) {
        int r = t / 136, c = t % 136;
        Bs[t] = (c < 128) ? tf32f(W_o1[r * 128 + c]) : 0.f;
    }
    if (tid < 128) sb[tid] = b_o1[tid];
    __syncthreads();

    float C[2][8][4] = {};
    gemm128<16, 132, 136>(As, Bs, C, tid);
    __syncthreads();

    const int lane = tid & 31, warp = tid >> 5;
    const int wm = (warp >> 1) * 32, wn = (warp & 1) * 64;
    const int gid = lane >> 2, tig = lane & 3;
#pragma unroll
    for (int i = 0; i < 2; ++i) {
        int r = wm + i * 16 + gid;
#pragma unroll
        for (int j = 0; j < 8; ++j) {
            int col = wn + j * 8 + 2 * tig;
            As[r * 132 + col]           = tf32f(ssp(C[i][j][0] + sb[col]));
            As[r * 132 + col + 1]       = tf32f(ssp(C[i][j][1] + sb[col + 1]));
            As[(r + 8) * 132 + col]     = tf32f(ssp(C[i][j][2] + sb[col]));
            As[(r + 8) * 132 + col + 1] = tf32f(ssp(C[i][j][3] + sb[col + 1]));
        }
    }
    for (int t = tid; t < 128 * 136; t += 256) {
        int r = t / 136, c = t % 136;
        Bs[t] = (c < 128) ? tf32f(W_o2[r * 128 + c]) : 0.f;
    }
    if (tid < 128) sb[tid] = b_o2[tid];
    __syncthreads();

    float C2[2][8][4] = {};
    gemm128<16, 132, 136>(As, Bs, C2, tid);

#pragma unroll
    for (int i = 0; i < 2; ++i)
#pragma unroll
        for (int h = 0; h < 2; ++h) {
            int row = r0 + wm + i * 16 + gid + h * 8;
            if (row < N_ATOMS)
#pragma unroll
                for (int j = 0; j < 8; ++j) {
                    int col = wn + j * 8 + 2 * tig;
                    float2 v = make_float2(C2[i][j][h * 2 + 0] + sb[col],
                                           C2[i][j][h * 2 + 1] + sb[col + 1]);
                    *reinterpret_cast<float2*>(&out[(size_t)row * 128 + col]) = v;
                }
        }
}

// ---------------------------------------------------------------------------
// Launch
// ---------------------------------------------------------------------------
extern "C" void kernel_launch(void* const* d_in, const int* in_sizes, int n_in,
                              void* d_out, int out_size) {
    const float* emb  = (const float*)d_in[0];
    const int*   pidx = (const int*)d_in[1];
    const float* fij  = (const float*)d_in[2];
    const float* cut  = (const float*)d_in[3];
    const float* W_in = (const float*)d_in[4];
    const float* W_f1 = (const float*)d_in[5];
    const float* b_f1 = (const float*)d_in[6];
    const float* W_f2 = (const float*)d_in[7];
    const float* b_f2 = (const float*)d_in[8];
    const float* W_o1 = (const float*)d_in[9];
    const float* b_o1 = (const float*)d_in[10];
    const float* W_o2 = (const float*)d_in[11];
    const float* b_o2 = (const float*)d_in[12];
    float* out = (float*)d_out;

    const int HALFSZ = 128 * 132 + 128 + 256;
    const int smemPair = (32 * 136 + 128 * 136 + 256 + 2 * HALFSZ) * 4;  // 226304 B
    const int smemGemm = (128 * 132 + 128 * 136 + 128) * 4;

    cudaFuncSetAttribute(k_pair, cudaFuncAttributeMaxDynamicSharedMemorySize, smemPair);
    cudaFuncSetAttribute(k_proj, cudaFuncAttributeMaxDynamicSharedMemorySize, smemGemm);
    cudaFuncSetAttribute(k_out,  cudaFuncAttributeMaxDynamicSharedMemorySize, smemGemm);

    const int NTILES = N_PAIRS / 128;  // 12500
    k_zero<<<(N_ATOMS * FDIM / 4 + 255) / 256, 256>>>();
    k_proj<<<(N_ATOMS + 127) / 128, 256, smemGemm>>>(emb, W_in);
    k_pair<<<148, 512, smemPair>>>(pidx, fij, cut, W_f1, b_f1, W_f2, b_f2, 0, NTILES / 2);
    k_pair<<<148, 512, smemPair>>>(pidx, fij, cut, W_f1, b_f1, W_f2, b_f2, NTILES / 2, NTILES - NTILES / 2);
    k_out<<<(N_ATOMS + 127) / 128, 256, smemGemm>>>(W_o1, b_o1, W_o2, b_o2, out);
}

// round 5
// speedup vs baseline: 2.0993x; 1.1273x over previous
#include <cuda_runtime.h>
#include <cstdint>

#define N_ATOMS 50000
#define N_PAIRS 1600000
#define LN2F 0.6931471805599453f

__device__ float g_x[(size_t)N_ATOMS * 128];
__device__ float g_acc[(size_t)N_ATOMS * 128];

// ---------------------------------------------------------------------------
// helpers
// ---------------------------------------------------------------------------
__device__ __forceinline__ uint32_t f2tf32(float x) {
    uint32_t u; asm("cvt.rna.tf32.f32 %0, %1;" : "=r"(u) : "f"(x)); return u;
}
__device__ __forceinline__ float tf32f(float x) { return __uint_as_float(f2tf32(x)); }

// fast shifted softplus: ln2 * (log2(1 + 2^(x*log2e)) - 1), MUFU-based
__device__ __forceinline__ float fssp(float x) {
    if (x > 60.f) return x - LN2F;
    float t, l;
    asm("ex2.approx.f32 %0, %1;" : "=f"(t) : "f"(x * 1.4426950408889634f));
    asm("lg2.approx.f32 %0, %1;" : "=f"(l) : "f"(t + 1.0f));
    return 0.69314718055994531f * (l - 1.0f);
}

__device__ __forceinline__ void red_add_v4(float* p, float a, float b, float c, float d) {
    asm volatile("red.global.add.v4.f32 [%0], {%1, %2, %3, %4};"
                 :: "l"(p), "f"(a), "f"(b), "f"(c), "f"(d) : "memory");
}
__device__ __forceinline__ void barh(int id) {
    asm volatile("bar.sync %0, 256;" :: "r"(id) : "memory");
}
__device__ __forceinline__ void mma8(float c[4], const uint32_t a[4], const uint32_t b[2]) {
    asm volatile(
        "mma.sync.aligned.m16n8k8.row.col.f32.tf32.tf32.f32 "
        "{%0,%1,%2,%3}, {%4,%5,%6,%7}, {%8,%9}, {%0,%1,%2,%3};\n"
        : "+f"(c[0]), "+f"(c[1]), "+f"(c[2]), "+f"(c[3])
        : "r"(a[0]), "r"(a[1]), "r"(a[2]), "r"(a[3]), "r"(b[0]), "r"(b[1]));
}

// ---------------------------------------------------------------------------
// Fragment-major smem layouts.
// A value at (row r, col c):  wr=r>>5, i=(r>>4)&1, k=c>>3,
//   lane=(r&7)*4+(c&3), slot=((r>>3)&1) + ((c>>2)&1)*2
//   idx = wr*(KST*256) + k*256 + i*128 + lane*4 + slot
// B value at (krow kk, col n): wcol=n>>6, j=(n>>3)&7, g=j>>1,
//   lane=(n&7)*4+(kk&3), slot=(j&1)*2 + ((kk>>2)&1)
//   idx = wcol*(KST*512) + k*512 + g*128 + lane*4 + slot
// ---------------------------------------------------------------------------
__device__ __forceinline__ int afrag_idx(int r, int c, int kst) {
    int lane = (r & 7) * 4 + (c & 3);
    int slot = ((r >> 3) & 1) + ((c >> 2) & 1) * 2;
    return (r >> 5) * (kst * 256) + (c >> 3) * 256 + ((r >> 4) & 1) * 128 + lane * 4 + slot;
}
__device__ __forceinline__ int bfrag_idx(int kk, int n, int kst) {
    int j = (n >> 3) & 7;
    int lane = (n & 7) * 4 + (kk & 3);
    int slot = (j & 1) * 2 + ((kk >> 2) & 1);
    return (n >> 6) * (kst * 512) + (kk >> 3) * 512 + (j >> 1) * 128 + lane * 4 + slot;
}

// 128x128xK tile GEMM from fragment-major tiles. 8 warps 4(m)x2(n).
template <int KST>
__device__ __forceinline__ void gemmF(const float* __restrict__ Af,
                                      const float* __restrict__ Bf,
                                      float C[2][8][4], int htid) {
    const int lane = htid & 31, warp = htid >> 5;
    const float4* A4 = (const float4*)Af + (warp >> 1) * (KST * 64) + lane;
    const float4* B4 = (const float4*)Bf + (warp & 1) * (KST * 128) + lane;
#pragma unroll
    for (int k = 0; k < KST; ++k) {
        float4 fa0 = A4[k * 64];
        float4 fa1 = A4[k * 64 + 32];
        uint32_t a[2][4] = {
            {__float_as_uint(fa0.x), __float_as_uint(fa0.y), __float_as_uint(fa0.z), __float_as_uint(fa0.w)},
            {__float_as_uint(fa1.x), __float_as_uint(fa1.y), __float_as_uint(fa1.z), __float_as_uint(fa1.w)}};
        uint32_t b[8][2];
#pragma unroll
        for (int g = 0; g < 4; ++g) {
            float4 fb = B4[k * 128 + g * 32];
            b[2 * g][0] = __float_as_uint(fb.x);
            b[2 * g][1] = __float_as_uint(fb.y);
            b[2 * g + 1][0] = __float_as_uint(fb.z);
            b[2 * g + 1][1] = __float_as_uint(fb.w);
        }
#pragma unroll
        for (int i = 0; i < 2; ++i)
#pragma unroll
            for (int j = 0; j < 8; ++j) mma8(C[i][j], a[i], b[j]);
    }
}

// smem float offsets for k_pair
#define OFF_BF2  0                      // W_f2 frags [2][16][4][32][4] = 16384 f
#define OFF_BF1  16384                  // W_f1 frags KST=3           = 3072 f
#define OFF_BB1  19456
#define OFF_BB2  19584
#define OFF_UNI0 19712
#define UNI_W    16896                  // max(A2 frags 16384, w-stage 128*132)
#define HALF_STRIDE (UNI_W + 128 + 256) // + scut + sidx  = 17280
#define SMEM_PAIR_F (OFF_UNI0 + 2 * HALF_STRIDE)  // 54272 f = 217088 B

// ---------------------------------------------------------------------------
// classic strided-smem GEMM for k_proj / k_out
// ---------------------------------------------------------------------------
template <int KSTEPS, int ASTRIDE, int BSTRIDE>
__device__ __forceinline__ void gemm128(const float* __restrict__ As,
                                        const float* __restrict__ Bs,
                                        float C[2][8][4], int tid) {
    const int lane = tid & 31, warp = tid >> 5;
    const int wm = (warp >> 1) * 32, wn = (warp & 1) * 64;
    const int gid = lane >> 2, tig = lane & 3;
#pragma unroll
    for (int k = 0; k < KSTEPS; ++k) {
        uint32_t a[2][4];
#pragma unroll
        for (int i = 0; i < 2; ++i) {
            const float* ap = As + (wm + i * 16 + gid) * ASTRIDE + k * 8 + tig;
            a[i][0] = __float_as_uint(ap[0]);
            a[i][1] = __float_as_uint(ap[8 * ASTRIDE]);
            a[i][2] = __float_as_uint(ap[4]);
            a[i][3] = __float_as_uint(ap[8 * ASTRIDE + 4]);
        }
        uint32_t b[8][2];
#pragma unroll
        for (int j = 0; j < 8; ++j) {
            const float* bp = Bs + (k * 8 + tig) * BSTRIDE + wn + j * 8 + gid;
            b[j][0] = __float_as_uint(bp[0]);
            b[j][1] = __float_as_uint(bp[4 * BSTRIDE]);
        }
#pragma unroll
        for (int i = 0; i < 2; ++i)
#pragma unroll
            for (int j = 0; j < 8; ++j) mma8(C[i][j], a[i], b[j]);
    }
}

__global__ void k_zero() {
    size_t i = (size_t)blockIdx.x * blockDim.x + threadIdx.x;
    if (i < (size_t)N_ATOMS * 32)
        reinterpret_cast<float4*>(g_acc)[i] = make_float4(0.f, 0.f, 0.f, 0.f);
}

__global__ __launch_bounds__(256, 1) void k_proj(const float* __restrict__ emb,
                                                 const float* __restrict__ W_in) {
    extern __shared__ float smem[];
    float* As = smem;
    float* Bs = smem + 128 * 132;
    const int tid = threadIdx.x;
    const int r0 = blockIdx.x * 128;
    for (int t = tid; t < 128 * 132; t += 256) {
        int r = t / 132, c = t % 132;
        float v = 0.f;
        if (c < 128 && (r0 + r) < N_ATOMS) v = emb[(size_t)(r0 + r) * 128 + c];
        As[t] = tf32f(v);
    }
    for (int t = tid; t < 128 * 136; t += 256) {
        int r = t / 136, c = t % 136;
        Bs[t] = (c < 128) ? tf32f(W_in[r * 128 + c]) : 0.f;
    }
    __syncthreads();
    float C[2][8][4] = {};
    gemm128<16, 132, 136>(As, Bs, C, tid);
    const int lane = tid & 31, warp = tid >> 5;
    const int wm = (warp >> 1) * 32, wn = (warp & 1) * 64;
    const int gid = lane >> 2, tig = lane & 3;
#pragma unroll
    for (int i = 0; i < 2; ++i)
#pragma unroll
        for (int h = 0; h < 2; ++h) {
            int row = r0 + wm + i * 16 + gid + h * 8;
            if (row < N_ATOMS)
#pragma unroll
                for (int j = 0; j < 8; ++j) {
                    int col = wn + j * 8 + 2 * tig;
                    float2 v = make_float2(C[i][j][h * 2], C[i][j][h * 2 + 1]);
                    *reinterpret_cast<float2*>(&g_x[(size_t)row * 128 + col]) = v;
                }
        }
}

// ---------------------------------------------------------------------------
// Persistent fused pair kernel: fragment-major tiles, reg-prefetch, fast ssp.
// 512 threads = two independent 256-thread halves.
// ---------------------------------------------------------------------------
__global__ __launch_bounds__(512, 1)
void k_pair(const int* __restrict__ pidx, const float* __restrict__ f_ij,
            const float* __restrict__ cut, const float* __restrict__ W_f1,
            const float* __restrict__ b_f1, const float* __restrict__ W_f2,
            const float* __restrict__ b_f2, int tile_base, int tile_count) {
    extern __shared__ float smem[];
    const int tid = threadIdx.x;
    const int half = tid >> 8;
    const int htid = tid & 255;

    float* Bf2 = smem + OFF_BF2;
    float* Bf1 = smem + OFF_BF1;
    float* uni = smem + OFF_UNI0 + half * HALF_STRIDE;
    float* scut = uni + UNI_W;
    int*   sidx = (int*)(scut + 128);

    // --- one-time staging: weight fragments + biases; zero GEMM1-A pad zone ---
    for (int t = tid; t < 128 * 128; t += 512) {
        int kk = t >> 7, n = t & 127;
        Bf2[bfrag_idx(kk, n, 16)] = tf32f(W_f2[kk * 128 + n]);
    }
    for (int t = tid; t < 24 * 128; t += 512) {
        int kk = t >> 7, n = t & 127;
        Bf1[bfrag_idx(kk, n, 3)] = (kk < 20) ? tf32f(W_f1[kk * 128 + n]) : 0.f;
    }
    if (tid < 128) smem[OFF_BB1 + tid] = b_f1[tid];
    else if (tid < 256) smem[OFF_BB2 + tid - 128] = b_f2[tid - 128];
    for (int t = htid; t < 3072; t += 256) uni[t] = 0.f;  // avoid stale NaN in A1 pad
    __syncthreads();

    const float* b1s = smem + OFF_BB1;
    const float* b2s = smem + OFF_BB2;
    const int bar = 1 + half;
    const int lane = htid & 31, warp = htid >> 5;
    const int wm = (warp >> 1) * 32, wn = (warp & 1) * 64;
    const int gid = lane >> 2, tig = lane & 3;

    const int end = tile_base + tile_count;
    const int step = (int)gridDim.x * 2;
    int tile = tile_base + (int)blockIdx.x * 2 + half;
    if (tile >= end) { return; }

    // prefetch tile 0
    const int prow = htid >> 1;          // pair row this thread stages
    const int pcol = (htid & 1) * 10;    // f_ij col base (10 floats each)
    float pf[10];
    float pcut = 0.f; int pii = 0, pjj = 0;
    {
        const float* src = f_ij + (size_t)(tile * 128 + prow) * 20 + pcol;
#pragma unroll
        for (int q = 0; q < 10; ++q) pf[q] = tf32f(__ldg(src + q));
        if (htid < 128) {
            pcut = __ldg(&cut[tile * 128 + htid]);
            pii  = __ldg(&pidx[tile * 128 + htid]);
            pjj  = __ldg(&pidx[N_PAIRS + tile * 128 + htid]);
        }
    }

    for (; tile < end; tile += step) {
        // S1: store prefetched tile into fragment-major A1 + meta
#pragma unroll
        for (int q = 0; q < 10; ++q) uni[afrag_idx(prow, pcol + q, 3)] = pf[q];
        if (htid < 128) { scut[htid] = pcut; sidx[htid] = pii; sidx[128 + htid] = pjj; }
        barh(bar);

        // prefetch next tile (overlaps all compute below)
        int nt = tile + step;
        if (nt < end) {
            const float* src = f_ij + (size_t)(nt * 128 + prow) * 20 + pcol;
#pragma unroll
            for (int q = 0; q < 10; ++q) pf[q] = tf32f(__ldg(src + q));
            if (htid < 128) {
                pcut = __ldg(&cut[nt * 128 + htid]);
                pii  = __ldg(&pidx[nt * 128 + htid]);
                pjj  = __ldg(&pidx[N_PAIRS + nt * 128 + htid]);
            }
        }

        // GEMM1: hidden_pre = f @ W_f1   (K=24)
        float C[2][8][4] = {};
        gemmF<3>(uni, Bf1, C, htid);
        barh(bar);  // A1 reads done before S3 overwrites union

        // S3: hidden = tf32(fssp(C + b1)) -> fragment-major A2
#pragma unroll
        for (int i = 0; i < 2; ++i) {
            int r = wm + i * 16 + gid;
#pragma unroll
            for (int j = 0; j < 8; ++j) {
                int col = wn + j * 8 + 2 * tig;
                uni[afrag_idx(r, col, 16)]           = tf32f(fssp(C[i][j][0] + b1s[col]));
                uni[afrag_idx(r, col + 1, 16)]       = tf32f(fssp(C[i][j][1] + b1s[col + 1]));
                uni[afrag_idx(r + 8, col, 16)]       = tf32f(fssp(C[i][j][2] + b1s[col]));
                uni[afrag_idx(r + 8, col + 1, 16)]   = tf32f(fssp(C[i][j][3] + b1s[col + 1]));
            }
        }
        barh(bar);

        // GEMM2: W_ij = hidden @ W_f2   (K=128)
        float C2[2][8][4] = {};
        gemmF<16>(uni, Bf2, C2, htid);
        barh(bar);  // A2 reads done before w-stage overwrites union

        // S5a: w = (C2 + b2) * cutoff -> union rows (stride 132)
#pragma unroll
        for (int i = 0; i < 2; ++i)
#pragma unroll
            for (int h = 0; h < 2; ++h) {
                int r = wm + i * 16 + gid + h * 8;
                float ct = scut[r];
#pragma unroll
                for (int j = 0; j < 8; ++j) {
                    int col = wn + j * 8 + 2 * tig;
                    float2 v = make_float2((C2[i][j][h * 2] + b2s[col]) * ct,
                                           (C2[i][j][h * 2 + 1] + b2s[col + 1]) * ct);
                    *reinterpret_cast<float2*>(&uni[r * 132 + col]) = v;
                }
            }
        barh(bar);

        // S5b: gather x[idx_j] * w, scatter-add acc[idx_i] (contig 64-f half-rows)
        {
            int r = htid >> 1, ch = (htid & 1) * 64;
            int aj = sidx[128 + r], ai = sidx[r];
            const float4* xr = (const float4*)(g_x + (size_t)aj * 128 + ch);
            float* ar = g_acc + (size_t)ai * 128 + ch;
            const float* wr = uni + r * 132 + ch;
#pragma unroll
            for (int q = 0; q < 16; ++q) {
                float4 xv = __ldg(xr + q);
                float4 wv = *(const float4*)(wr + 4 * q);
                red_add_v4(ar + 4 * q, wv.x * xv.x, wv.y * xv.y, wv.z * xv.z, wv.w * xv.w);
            }
        }
        barh(bar);  // epilogue reads done before next S1 overwrites union
    }
}

__global__ __launch_bounds__(256, 1) void k_out(const float* __restrict__ W_o1,
                                                const float* __restrict__ b_o1,
                                                const float* __restrict__ W_o2,
                                                const float* __restrict__ b_o2,
                                                float* __restrict__ out) {
    extern __shared__ float smem[];
    float* As = smem;
    float* Bs = smem + 128 * 132;
    float* sbv = Bs + 128 * 136;
    const int tid = threadIdx.x;
    const int r0 = blockIdx.x * 128;
    for (int t = tid; t < 128 * 132; t += 256) {
        int r = t / 132, c = t % 132;
        float v = 0.f;
        if (c < 128 && (r0 + r) < N_ATOMS) v = g_acc[(size_t)(r0 + r) * 128 + c];
        As[t] = tf32f(v);
    }
    for (int t = tid; t < 128 * 136; t += 256) {
        int r = t / 136, c = t % 136;
        Bs[t] = (c < 128) ? tf32f(W_o1[r * 128 + c]) : 0.f;
    }
    if (tid < 128) sbv[tid] = b_o1[tid];
    __syncthreads();
    float C[2][8][4] = {};
    gemm128<16, 132, 136>(As, Bs, C, tid);
    __syncthreads();
    const int lane = tid & 31, warp = tid >> 5;
    const int wm = (warp >> 1) * 32, wn = (warp & 1) * 64;
    const int gid = lane >> 2, tig = lane & 3;
#pragma unroll
    for (int i = 0; i < 2; ++i) {
        int r = wm + i * 16 + gid;
#pragma unroll
        for (int j = 0; j < 8; ++j) {
            int col = wn + j * 8 + 2 * tig;
            As[r * 132 + col]           = tf32f(fssp(C[i][j][0] + sbv[col]));
            As[r * 132 + col + 1]       = tf32f(fssp(C[i][j][1] + sbv[col + 1]));
            As[(r + 8) * 132 + col]     = tf32f(fssp(C[i][j][2] + sbv[col]));
            As[(r + 8) * 132 + col + 1] = tf32f(fssp(C[i][j][3] + sbv[col + 1]));
        }
    }
    for (int t = tid; t < 128 * 136; t += 256) {
        int r = t / 136, c = t % 136;
        Bs[t] = (c < 128) ? tf32f(W_o2[r * 128 + c]) : 0.f;
    }
    if (tid < 128) sbv[tid] = b_o2[tid];
    __syncthreads();
    float C2[2][8][4] = {};
    gemm128<16, 132, 136>(As, Bs, C2, tid);
#pragma unroll
    for (int i = 0; i < 2; ++i)
#pragma unroll
        for (int h = 0; h < 2; ++h) {
            int row = r0 + wm + i * 16 + gid + h * 8;
            if (row < N_ATOMS)
#pragma unroll
                for (int j = 0; j < 8; ++j) {
                    int col = wn + j * 8 + 2 * tig;
                    float2 v = make_float2(C2[i][j][h * 2] + sbv[col],
                                           C2[i][j][h * 2 + 1] + sbv[col + 1]);
                    *reinterpret_cast<float2*>(&out[(size_t)row * 128 + col]) = v;
                }
        }
}

extern "C" void kernel_launch(void* const* d_in, const int* in_sizes, int n_in,
                              void* d_out, int out_size) {
    const float* emb  = (const float*)d_in[0];
    const int*   pidx = (const int*)d_in[1];
    const float* fij  = (const float*)d_in[2];
    const float* cut  = (const float*)d_in[3];
    const float* W_in = (const float*)d_in[4];
    const float* W_f1 = (const float*)d_in[5];
    const float* b_f1 = (const float*)d_in[6];
    const float* W_f2 = (const float*)d_in[7];
    const float* b_f2 = (const float*)d_in[8];
    const float* W_o1 = (const float*)d_in[9];
    const float* b_o1 = (const float*)d_in[10];
    const float* W_o2 = (const float*)d_in[11];
    const float* b_o2 = (const float*)d_in[12];
    float* out = (float*)d_out;

    const int smemPair = SMEM_PAIR_F * 4;  // 217088 B
    const int smemGemm = (128 * 132 + 128 * 136 + 128) * 4;

    cudaFuncSetAttribute(k_pair, cudaFuncAttributeMaxDynamicSharedMemorySize, smemPair);
    cudaFuncSetAttribute(k_proj, cudaFuncAttributeMaxDynamicSharedMemorySize, smemGemm);
    cudaFuncSetAttribute(k_out,  cudaFuncAttributeMaxDynamicSharedMemorySize, smemGemm);

    const int NT = N_PAIRS / 128;  // 12500
    k_zero<<<(N_ATOMS * 32 + 255) / 256, 256>>>();
    k_proj<<<(N_ATOMS + 127) / 128, 256, smemGemm>>>(emb, W_in);
    k_pair<<<148, 512, smemPair>>>(pidx, fij, cut, W_f1, b_f1, W_f2, b_f2, 0, NT / 2);
    k_pair<<<148, 512, smemPair>>>(pidx, fij, cut, W_f1, b_f1, W_f2, b_f2, NT / 2, NT - NT / 2);
    k_out<<<(N_ATOMS + 127) / 128, 256, smemGemm>>>(W_o1, b_o1, W_o2, b_o2, out);
}

// round 6
// speedup vs baseline: 2.4787x; 1.1807x over previous
#include <cuda_runtime.h>
#include <cstdint>

#define N_ATOMS 50000
#define N_PAIRS 1600000
#define LN2F 0.6931471805599453f
#define CAP 96

__device__ float g_x[(size_t)N_ATOMS * 128];
__device__ float g_acc[(size_t)N_ATOMS * 128];
__device__ float g_w[(size_t)N_PAIRS * 128];      // cutoff-weighted filters
__device__ int   g_cnt[N_ATOMS];
__device__ int   g_bucket[(size_t)N_ATOMS * CAP];

// ---------------------------------------------------------------------------
// helpers
// ---------------------------------------------------------------------------
__device__ __forceinline__ uint32_t f2tf32(float x) {
    uint32_t u; asm("cvt.rna.tf32.f32 %0, %1;" : "=r"(u) : "f"(x)); return u;
}
__device__ __forceinline__ float tf32f(float x) { return __uint_as_float(f2tf32(x)); }

__device__ __forceinline__ float fssp(float x) {
    if (x > 60.f) return x - LN2F;
    float t, l;
    asm("ex2.approx.f32 %0, %1;" : "=f"(t) : "f"(x * 1.4426950408889634f));
    asm("lg2.approx.f32 %0, %1;" : "=f"(l) : "f"(t + 1.0f));
    return 0.69314718055994531f * (l - 1.0f);
}
__device__ __forceinline__ void barh(int id) {
    asm volatile("bar.sync %0, 256;" :: "r"(id) : "memory");
}
__device__ __forceinline__ void mma8(float c[4], const uint32_t a[4], const uint32_t b[2]) {
    asm volatile(
        "mma.sync.aligned.m16n8k8.row.col.f32.tf32.tf32.f32 "
        "{%0,%1,%2,%3}, {%4,%5,%6,%7}, {%8,%9}, {%0,%1,%2,%3};\n"
        : "+f"(c[0]), "+f"(c[1]), "+f"(c[2]), "+f"(c[3])
        : "r"(a[0]), "r"(a[1]), "r"(a[2]), "r"(a[3]), "r"(b[0]), "r"(b[1]));
}

// ---------------------------------------------------------------------------
// Fragment-major smem layouts (see round-5 derivation)
// ---------------------------------------------------------------------------
__device__ __forceinline__ int afrag_idx(int r, int c, int kst) {
    int lane = (r & 7) * 4 + (c & 3);
    int slot = ((r >> 3) & 1) + ((c >> 2) & 1) * 2;
    return (r >> 5) * (kst * 256) + (c >> 3) * 256 + ((r >> 4) & 1) * 128 + lane * 4 + slot;
}
__device__ __forceinline__ int bfrag_idx(int kk, int n, int kst) {
    int j = (n >> 3) & 7;
    int lane = (n & 7) * 4 + (kk & 3);
    int slot = (j & 1) * 2 + ((kk >> 2) & 1);
    return (n >> 6) * (kst * 512) + (kk >> 3) * 512 + (j >> 1) * 128 + lane * 4 + slot;
}

template <int KST>
__device__ __forceinline__ void gemmF(const float* __restrict__ Af,
                                      const float* __restrict__ Bf,
                                      float C[2][8][4], int htid) {
    const int lane = htid & 31, warp = htid >> 5;
    const float4* A4 = (const float4*)Af + (warp >> 1) * (KST * 64) + lane;
    const float4* B4 = (const float4*)Bf + (warp & 1) * (KST * 128) + lane;
#pragma unroll
    for (int k = 0; k < KST; ++k) {
        float4 fa0 = A4[k * 64];
        float4 fa1 = A4[k * 64 + 32];
        uint32_t a[2][4] = {
            {__float_as_uint(fa0.x), __float_as_uint(fa0.y), __float_as_uint(fa0.z), __float_as_uint(fa0.w)},
            {__float_as_uint(fa1.x), __float_as_uint(fa1.y), __float_as_uint(fa1.z), __float_as_uint(fa1.w)}};
        uint32_t b[8][2];
#pragma unroll
        for (int g = 0; g < 4; ++g) {
            float4 fb = B4[k * 128 + g * 32];
            b[2 * g][0] = __float_as_uint(fb.x);
            b[2 * g][1] = __float_as_uint(fb.y);
            b[2 * g + 1][0] = __float_as_uint(fb.z);
            b[2 * g + 1][1] = __float_as_uint(fb.w);
        }
#pragma unroll
        for (int i = 0; i < 2; ++i)
#pragma unroll
            for (int j = 0; j < 8; ++j) mma8(C[i][j], a[i], b[j]);
    }
}

// smem float offsets for k_pair
#define OFF_BF2  0
#define OFF_BF1  16384
#define OFF_BB1  19456
#define OFF_BB2  19584
#define OFF_UNI0 19712
#define UNI_W    16896
#define HALF_STRIDE (UNI_W + 128)
#define SMEM_PAIR_F (OFF_UNI0 + 2 * HALF_STRIDE)  // 53760 f = 215040 B

// classic strided-smem GEMM for k_proj / k_out
template <int KSTEPS, int ASTRIDE, int BSTRIDE>
__device__ __forceinline__ void gemm128(const float* __restrict__ As,
                                        const float* __restrict__ Bs,
                                        float C[2][8][4], int tid) {
    const int lane = tid & 31, warp = tid >> 5;
    const int wm = (warp >> 1) * 32, wn = (warp & 1) * 64;
    const int gid = lane >> 2, tig = lane & 3;
#pragma unroll
    for (int k = 0; k < KSTEPS; ++k) {
        uint32_t a[2][4];
#pragma unroll
        for (int i = 0; i < 2; ++i) {
            const float* ap = As + (wm + i * 16 + gid) * ASTRIDE + k * 8 + tig;
            a[i][0] = __float_as_uint(ap[0]);
            a[i][1] = __float_as_uint(ap[8 * ASTRIDE]);
            a[i][2] = __float_as_uint(ap[4]);
            a[i][3] = __float_as_uint(ap[8 * ASTRIDE + 4]);
        }
        uint32_t b[8][2];
#pragma unroll
        for (int j = 0; j < 8; ++j) {
            const float* bp = Bs + (k * 8 + tig) * BSTRIDE + wn + j * 8 + gid;
            b[j][0] = __float_as_uint(bp[0]);
            b[j][1] = __float_as_uint(bp[4 * BSTRIDE]);
        }
#pragma unroll
        for (int i = 0; i < 2; ++i)
#pragma unroll
            for (int j = 0; j < 8; ++j) mma8(C[i][j], a[i], b[j]);
    }
}

// ---------------------------------------------------------------------------
// bucketing
// ---------------------------------------------------------------------------
__global__ void k_czero() {
    int i = blockIdx.x * blockDim.x + threadIdx.x;
    if (i < N_ATOMS) g_cnt[i] = 0;
}
__global__ void k_bucket(const int* __restrict__ pidx) {
    int p = blockIdx.x * blockDim.x + threadIdx.x;
    if (p < N_PAIRS) {
        int i = __ldg(&pidx[p]);
        int slot = atomicAdd(&g_cnt[i], 1);
        if (slot < CAP) g_bucket[(size_t)i * CAP + slot] = p;
    }
}

// ---------------------------------------------------------------------------
// x = atomic_embedding @ W_in -> g_x
// ---------------------------------------------------------------------------
__global__ __launch_bounds__(256, 1) void k_proj(const float* __restrict__ emb,
                                                 const float* __restrict__ W_in) {
    extern __shared__ float smem[];
    float* As = smem;
    float* Bs = smem + 128 * 132;
    const int tid = threadIdx.x;
    const int r0 = blockIdx.x * 128;
    for (int t = tid; t < 128 * 132; t += 256) {
        int r = t / 132, c = t % 132;
        float v = 0.f;
        if (c < 128 && (r0 + r) < N_ATOMS) v = emb[(size_t)(r0 + r) * 128 + c];
        As[t] = tf32f(v);
    }
    for (int t = tid; t < 128 * 136; t += 256) {
        int r = t / 136, c = t % 136;
        Bs[t] = (c < 128) ? tf32f(W_in[r * 128 + c]) : 0.f;
    }
    __syncthreads();
    float C[2][8][4] = {};
    gemm128<16, 132, 136>(As, Bs, C, tid);
    const int lane = tid & 31, warp = tid >> 5;
    const int wm = (warp >> 1) * 32, wn = (warp & 1) * 64;
    const int gid = lane >> 2, tig = lane & 3;
#pragma unroll
    for (int i = 0; i < 2; ++i)
#pragma unroll
        for (int h = 0; h < 2; ++h) {
            int row = r0 + wm + i * 16 + gid + h * 8;
            if (row < N_ATOMS)
#pragma unroll
                for (int j = 0; j < 8; ++j) {
                    int col = wn + j * 8 + 2 * tig;
                    float2 v = make_float2(C[i][j][h * 2], C[i][j][h * 2 + 1]);
                    *reinterpret_cast<float2*>(&g_x[(size_t)row * 128 + col]) = v;
                }
        }
}

// ---------------------------------------------------------------------------
// Phase A: persistent filter-network GEMMs; coalesced write of w to g_w.
// ---------------------------------------------------------------------------
__global__ __launch_bounds__(512, 1)
void k_pair(const float* __restrict__ f_ij, const float* __restrict__ cut,
            const float* __restrict__ W_f1, const float* __restrict__ b_f1,
            const float* __restrict__ W_f2, const float* __restrict__ b_f2,
            int tile_base, int tile_count) {
    extern __shared__ float smem[];
    const int tid = threadIdx.x;
    const int half = tid >> 8;
    const int htid = tid & 255;

    float* Bf2 = smem + OFF_BF2;
    float* Bf1 = smem + OFF_BF1;
    float* uni = smem + OFF_UNI0 + half * HALF_STRIDE;
    float* scut = uni + UNI_W;

    for (int t = tid; t < 128 * 128; t += 512) {
        int kk = t >> 7, n = t & 127;
        Bf2[bfrag_idx(kk, n, 16)] = tf32f(W_f2[kk * 128 + n]);
    }
    for (int t = tid; t < 24 * 128; t += 512) {
        int kk = t >> 7, n = t & 127;
        Bf1[bfrag_idx(kk, n, 3)] = (kk < 20) ? tf32f(W_f1[kk * 128 + n]) : 0.f;
    }
    if (tid < 128) smem[OFF_BB1 + tid] = b_f1[tid];
    else if (tid < 256) smem[OFF_BB2 + tid - 128] = b_f2[tid - 128];
    for (int t = htid; t < 3072; t += 256) uni[t] = 0.f;
    __syncthreads();

    const float* b1s = smem + OFF_BB1;
    const float* b2s = smem + OFF_BB2;
    const int bar = 1 + half;
    const int lane = htid & 31, warp = htid >> 5;
    const int wm = (warp >> 1) * 32, wn = (warp & 1) * 64;
    const int gid = lane >> 2, tig = lane & 3;

    const int end = tile_base + tile_count;
    const int step = (int)gridDim.x * 2;
    int tile = tile_base + (int)blockIdx.x * 2 + half;
    if (tile >= end) return;

    const int prow = htid >> 1;
    const int pcol = (htid & 1) * 10;
    float pf[10];
    float pcut = 0.f;
    {
        const float* src = f_ij + (size_t)(tile * 128 + prow) * 20 + pcol;
#pragma unroll
        for (int q = 0; q < 10; ++q) pf[q] = tf32f(__ldg(src + q));
        if (htid < 128) pcut = __ldg(&cut[tile * 128 + htid]);
    }

    for (; tile < end; tile += step) {
        const int p0 = tile * 128;

        // S1: store prefetched f_ij into fragment-major A1 + cutoff
#pragma unroll
        for (int q = 0; q < 10; ++q) uni[afrag_idx(prow, pcol + q, 3)] = pf[q];
        if (htid < 128) scut[htid] = pcut;
        barh(bar);

        // prefetch next tile
        int nt = tile + step;
        if (nt < end) {
            const float* src = f_ij + (size_t)(nt * 128 + prow) * 20 + pcol;
#pragma unroll
            for (int q = 0; q < 10; ++q) pf[q] = tf32f(__ldg(src + q));
            if (htid < 128) pcut = __ldg(&cut[nt * 128 + htid]);
        }

        // GEMM1 (K=24)
        float C[2][8][4] = {};
        gemmF<3>(uni, Bf1, C, htid);
        barh(bar);

        // hidden = tf32(fssp(C+b1)) -> fragment-major A2
#pragma unroll
        for (int i = 0; i < 2; ++i) {
            int r = wm + i * 16 + gid;
#pragma unroll
            for (int j = 0; j < 8; ++j) {
                int col = wn + j * 8 + 2 * tig;
                uni[afrag_idx(r, col, 16)]         = tf32f(fssp(C[i][j][0] + b1s[col]));
                uni[afrag_idx(r, col + 1, 16)]     = tf32f(fssp(C[i][j][1] + b1s[col + 1]));
                uni[afrag_idx(r + 8, col, 16)]     = tf32f(fssp(C[i][j][2] + b1s[col]));
                uni[afrag_idx(r + 8, col + 1, 16)] = tf32f(fssp(C[i][j][3] + b1s[col + 1]));
            }
        }
        barh(bar);

        // GEMM2 (K=128)
        float C2[2][8][4] = {};
        gemmF<16>(uni, Bf2, C2, htid);
        barh(bar);

        // stage w = (C2+b2)*cut rows (stride 132)
#pragma unroll
        for (int i = 0; i < 2; ++i)
#pragma unroll
            for (int h = 0; h < 2; ++h) {
                int r = wm + i * 16 + gid + h * 8;
                float ct = scut[r];
#pragma unroll
                for (int j = 0; j < 8; ++j) {
                    int col = wn + j * 8 + 2 * tig;
                    float2 v = make_float2((C2[i][j][h * 2] + b2s[col]) * ct,
                                           (C2[i][j][h * 2 + 1] + b2s[col + 1]) * ct);
                    *reinterpret_cast<float2*>(&uni[r * 132 + col]) = v;
                }
            }
        barh(bar);

        // coalesced write-out: warp = full 512B rows
#pragma unroll
        for (int rr = 0; rr < 16; ++rr) {
            int row = warp * 16 + rr;
            float4 v = *reinterpret_cast<const float4*>(uni + row * 132 + lane * 4);
            *((float4*)(g_w + (size_t)(p0 + row) * 128) + lane) = v;
        }
        barh(bar);
    }
}

// ---------------------------------------------------------------------------
// Phase B: one warp per atom sums w[p] * x[idx_j[p]]
// ---------------------------------------------------------------------------
__global__ __launch_bounds__(256, 2) void k_gather(const int* __restrict__ pidx) {
    int atom = (blockIdx.x * 256 + threadIdx.x) >> 5;
    int lane = threadIdx.x & 31;
    if (atom >= N_ATOMS) return;
    int cnt = __ldg(&g_cnt[atom]);
    if (cnt > CAP) cnt = CAP;
    const int* bucket = g_bucket + (size_t)atom * CAP;
    float4 acc = make_float4(0.f, 0.f, 0.f, 0.f);

    if (cnt > 0) {
        int p = __ldg(&bucket[0]);
        int aj = __ldg(&pidx[N_PAIRS + p]);
        for (int t = 0; t < cnt; ++t) {
            const float4 w = __ldg((const float4*)(g_w + (size_t)p * 128) + lane);
            const float4 x = __ldg((const float4*)(g_x + (size_t)aj * 128) + lane);
            if (t + 1 < cnt) {  // prefetch next indices
                p = __ldg(&bucket[t + 1]);
                aj = __ldg(&pidx[N_PAIRS + p]);
            }
            acc.x += w.x * x.x; acc.y += w.y * x.y;
            acc.z += w.z * x.z; acc.w += w.w * x.w;
        }
    }
    *((float4*)(g_acc + (size_t)atom * 128) + lane) = acc;
}

// ---------------------------------------------------------------------------
// Output MLP
// ---------------------------------------------------------------------------
__global__ __launch_bounds__(256, 1) void k_out(const float* __restrict__ W_o1,
                                                const float* __restrict__ b_o1,
                                                const float* __restrict__ W_o2,
                                                const float* __restrict__ b_o2,
                                                float* __restrict__ out) {
    extern __shared__ float smem[];
    float* As = smem;
    float* Bs = smem + 128 * 132;
    float* sbv = Bs + 128 * 136;
    const int tid = threadIdx.x;
    const int r0 = blockIdx.x * 128;
    for (int t = tid; t < 128 * 132; t += 256) {
        int r = t / 132, c = t % 132;
        float v = 0.f;
        if (c < 128 && (r0 + r) < N_ATOMS) v = g_acc[(size_t)(r0 + r) * 128 + c];
        As[t] = tf32f(v);
    }
    for (int t = tid; t < 128 * 136; t += 256) {
        int r = t / 136, c = t % 136;
        Bs[t] = (c < 128) ? tf32f(W_o1[r * 128 + c]) : 0.f;
    }
    if (tid < 128) sbv[tid] = b_o1[tid];
    __syncthreads();
    float C[2][8][4] = {};
    gemm128<16, 132, 136>(As, Bs, C, tid);
    __syncthreads();
    const int lane = tid & 31, warp = tid >> 5;
    const int wm = (warp >> 1) * 32, wn = (warp & 1) * 64;
    const int gid = lane >> 2, tig = lane & 3;
#pragma unroll
    for (int i = 0; i < 2; ++i) {
        int r = wm + i * 16 + gid;
#pragma unroll
        for (int j = 0; j < 8; ++j) {
            int col = wn + j * 8 + 2 * tig;
            As[r * 132 + col]           = tf32f(fssp(C[i][j][0] + sbv[col]));
            As[r * 132 + col + 1]       = tf32f(fssp(C[i][j][1] + sbv[col + 1]));
            As[(r + 8) * 132 + col]     = tf32f(fssp(C[i][j][2] + sbv[col]));
            As[(r + 8) * 132 + col + 1] = tf32f(fssp(C[i][j][3] + sbv[col + 1]));
        }
    }
    for (int t = tid; t < 128 * 136; t += 256) {
        int r = t / 136, c = t % 136;
        Bs[t] = (c < 128) ? tf32f(W_o2[r * 128 + c]) : 0.f;
    }
    if (tid < 128) sbv[tid] = b_o2[tid];
    __syncthreads();
    float C2[2][8][4] = {};
    gemm128<16, 132, 136>(As, Bs, C2, tid);
#pragma unroll
    for (int i = 0; i < 2; ++i)
#pragma unroll
        for (int h = 0; h < 2; ++h) {
            int row = r0 + wm + i * 16 + gid + h * 8;
            if (row < N_ATOMS)
#pragma unroll
                for (int j = 0; j < 8; ++j) {
                    int col = wn + j * 8 + 2 * tig;
                    float2 v = make_float2(C2[i][j][h * 2] + sbv[col],
                                           C2[i][j][h * 2 + 1] + sbv[col + 1]);
                    *reinterpret_cast<float2*>(&out[(size_t)row * 128 + col]) = v;
                }
        }
}

extern "C" void kernel_launch(void* const* d_in, const int* in_sizes, int n_in,
                              void* d_out, int out_size) {
    const float* emb  = (const float*)d_in[0];
    const int*   pidx = (const int*)d_in[1];
    const float* fij  = (const float*)d_in[2];
    const float* cut  = (const float*)d_in[3];
    const float* W_in = (const float*)d_in[4];
    const float* W_f1 = (const float*)d_in[5];
    const float* b_f1 = (const float*)d_in[6];
    const float* W_f2 = (const float*)d_in[7];
    const float* b_f2 = (const float*)d_in[8];
    const float* W_o1 = (const float*)d_in[9];
    const float* b_o1 = (const float*)d_in[10];
    const float* W_o2 = (const float*)d_in[11];
    const float* b_o2 = (const float*)d_in[12];
    float* out = (float*)d_out;

    const int smemPair = SMEM_PAIR_F * 4;  // 215040 B
    const int smemGemm = (128 * 132 + 128 * 136 + 128) * 4;

    cudaFuncSetAttribute(k_pair, cudaFuncAttributeMaxDynamicSharedMemorySize, smemPair);
    cudaFuncSetAttribute(k_proj, cudaFuncAttributeMaxDynamicSharedMemorySize, smemGemm);
    cudaFuncSetAttribute(k_out,  cudaFuncAttributeMaxDynamicSharedMemorySize, smemGemm);

    const int NT = N_PAIRS / 128;  // 12500
    k_czero<<<(N_ATOMS + 255) / 256, 256>>>();
    k_bucket<<<(N_PAIRS + 255) / 256, 256>>>(pidx);
    k_proj<<<(N_ATOMS + 127) / 128, 256, smemGemm>>>(emb, W_in);
    k_pair<<<148, 512, smemPair>>>(fij, cut, W_f1, b_f1, W_f2, b_f2, 0, NT / 2);
    k_pair<<<148, 512, smemPair>>>(fij, cut, W_f1, b_f1, W_f2, b_f2, NT / 2, NT - NT / 2);
    k_gather<<<(N_ATOMS * 32 + 255) / 256, 256>>>(pidx);
    k_out<<<(N_ATOMS + 127) / 128, 256, smemGemm>>>(W_o1, b_o1, W_o2, b_o2, out);
}

// round 7
// speedup vs baseline: 2.9184x; 1.1774x over previous
#include <cuda_runtime.h>
#include <cstdint>

#define N_ATOMS 50000
#define N_PAIRS 1600000
#define LN2F 0.6931471805599453f
#define CAP 96

__device__ float g_x[(size_t)N_ATOMS * 128];
__device__ float g_acc[(size_t)N_ATOMS * 128];
__device__ float g_w[(size_t)N_PAIRS * 128];
__device__ int   g_cnt[N_ATOMS];
__device__ int2  g_bucket[(size_t)N_ATOMS * CAP];

// ---------------------------------------------------------------------------
// helpers
// ---------------------------------------------------------------------------
__device__ __forceinline__ uint32_t f2tf32(float x) {
    uint32_t u; asm("cvt.rna.tf32.f32 %0, %1;" : "=r"(u) : "f"(x)); return u;
}
__device__ __forceinline__ float tf32f(float x) { return __uint_as_float(f2tf32(x)); }

__device__ __forceinline__ float fssp(float x) {
    if (x > 60.f) return x - LN2F;
    float t, l;
    asm("ex2.approx.f32 %0, %1;" : "=f"(t) : "f"(x * 1.4426950408889634f));
    asm("lg2.approx.f32 %0, %1;" : "=f"(l) : "f"(t + 1.0f));
    return 0.69314718055994531f * (l - 1.0f);
}
__device__ __forceinline__ void barh(int id) {
    asm volatile("bar.sync %0, 256;" :: "r"(id) : "memory");
}
__device__ __forceinline__ void mma8(float c[4], const uint32_t a[4], const uint32_t b[2]) {
    asm volatile(
        "mma.sync.aligned.m16n8k8.row.col.f32.tf32.tf32.f32 "
        "{%0,%1,%2,%3}, {%4,%5,%6,%7}, {%8,%9}, {%0,%1,%2,%3};\n"
        : "+f"(c[0]), "+f"(c[1]), "+f"(c[2]), "+f"(c[3])
        : "r"(a[0]), "r"(a[1]), "r"(a[2]), "r"(a[3]), "r"(b[0]), "r"(b[1]));
}
__device__ __forceinline__ float shfl_bfly(float v, int m) {
    return __shfl_xor_sync(0xffffffffu, v, m);
}

// ---------------------------------------------------------------------------
// Fragment-major smem layouts (round-5 derivation)
// ---------------------------------------------------------------------------
__device__ __forceinline__ int afrag_idx(int r, int c, int kst) {
    int lane = (r & 7) * 4 + (c & 3);
    int slot = ((r >> 3) & 1) + ((c >> 2) & 1) * 2;
    return (r >> 5) * (kst * 256) + (c >> 3) * 256 + ((r >> 4) & 1) * 128 + lane * 4 + slot;
}
__device__ __forceinline__ int bfrag_idx(int kk, int n, int kst) {
    int j = (n >> 3) & 7;
    int lane = (n & 7) * 4 + (kk & 3);
    int slot = (j & 1) * 2 + ((kk >> 2) & 1);
    return (n >> 6) * (kst * 512) + (kk >> 3) * 512 + (j >> 1) * 128 + lane * 4 + slot;
}

template <int KST>
__device__ __forceinline__ void gemmF(const float* __restrict__ Af,
                                      const float* __restrict__ Bf,
                                      float C[2][8][4], int htid) {
    const int lane = htid & 31, warp = htid >> 5;
    const float4* A4 = (const float4*)Af + (warp >> 1) * (KST * 64) + lane;
    const float4* B4 = (const float4*)Bf + (warp & 1) * (KST * 128) + lane;
#pragma unroll
    for (int k = 0; k < KST; ++k) {
        float4 fa0 = A4[k * 64];
        float4 fa1 = A4[k * 64 + 32];
        uint32_t a[2][4] = {
            {__float_as_uint(fa0.x), __float_as_uint(fa0.y), __float_as_uint(fa0.z), __float_as_uint(fa0.w)},
            {__float_as_uint(fa1.x), __float_as_uint(fa1.y), __float_as_uint(fa1.z), __float_as_uint(fa1.w)}};
        uint32_t b[8][2];
#pragma unroll
        for (int g = 0; g < 4; ++g) {
            float4 fb = B4[k * 128 + g * 32];
            b[2 * g][0] = __float_as_uint(fb.x);
            b[2 * g][1] = __float_as_uint(fb.y);
            b[2 * g + 1][0] = __float_as_uint(fb.z);
            b[2 * g + 1][1] = __float_as_uint(fb.w);
        }
#pragma unroll
        for (int i = 0; i < 2; ++i)
#pragma unroll
            for (int j = 0; j < 8; ++j) mma8(C[i][j], a[i], b[j]);
    }
}

// smem float offsets for k_pair
#define OFF_BF2  0
#define OFF_BF1  16384
#define OFF_BB1  19456
#define OFF_BB2  19584
#define OFF_UNI0 19712
#define UNI_W    16384
#define HALF_STRIDE (UNI_W + 128)
#define SMEM_PAIR_F (OFF_UNI0 + 2 * HALF_STRIDE)  // 52736 f = 210944 B

// classic strided-smem GEMM for k_proj / k_out
template <int KSTEPS, int ASTRIDE, int BSTRIDE>
__device__ __forceinline__ void gemm128(const float* __restrict__ As,
                                        const float* __restrict__ Bs,
                                        float C[2][8][4], int tid) {
    const int lane = tid & 31, warp = tid >> 5;
    const int wm = (warp >> 1) * 32, wn = (warp & 1) * 64;
    const int gid = lane >> 2, tig = lane & 3;
#pragma unroll
    for (int k = 0; k < KSTEPS; ++k) {
        uint32_t a[2][4];
#pragma unroll
        for (int i = 0; i < 2; ++i) {
            const float* ap = As + (wm + i * 16 + gid) * ASTRIDE + k * 8 + tig;
            a[i][0] = __float_as_uint(ap[0]);
            a[i][1] = __float_as_uint(ap[8 * ASTRIDE]);
            a[i][2] = __float_as_uint(ap[4]);
            a[i][3] = __float_as_uint(ap[8 * ASTRIDE + 4]);
        }
        uint32_t b[8][2];
#pragma unroll
        for (int j = 0; j < 8; ++j) {
            const float* bp = Bs + (k * 8 + tig) * BSTRIDE + wn + j * 8 + gid;
            b[j][0] = __float_as_uint(bp[0]);
            b[j][1] = __float_as_uint(bp[4 * BSTRIDE]);
        }
#pragma unroll
        for (int i = 0; i < 2; ++i)
#pragma unroll
            for (int j = 0; j < 8; ++j) mma8(C[i][j], a[i], b[j]);
    }
}

// ---------------------------------------------------------------------------
// bucketing
// ---------------------------------------------------------------------------
__global__ void k_czero() {
    int i = blockIdx.x * blockDim.x + threadIdx.x;
    if (i < N_ATOMS) g_cnt[i] = 0;
}
__global__ void k_bucket(const int* __restrict__ pidx) {
    int p = blockIdx.x * blockDim.x + threadIdx.x;
    if (p < N_PAIRS) {
        int i = __ldg(&pidx[p]);
        int j = __ldg(&pidx[N_PAIRS + p]);
        int slot = atomicAdd(&g_cnt[i], 1);
        if (slot < CAP) g_bucket[(size_t)i * CAP + slot] = make_int2(p, j);
    }
}

// ---------------------------------------------------------------------------
// x = atomic_embedding @ W_in -> g_x
// ---------------------------------------------------------------------------
__global__ __launch_bounds__(256, 1) void k_proj(const float* __restrict__ emb,
                                                 const float* __restrict__ W_in) {
    extern __shared__ float smem[];
    float* As = smem;
    float* Bs = smem + 128 * 132;
    const int tid = threadIdx.x;
    const int r0 = blockIdx.x * 128;
    for (int t = tid; t < 128 * 132; t += 256) {
        int r = t / 132, c = t % 132;
        float v = 0.f;
        if (c < 128 && (r0 + r) < N_ATOMS) v = emb[(size_t)(r0 + r) * 128 + c];
        As[t] = tf32f(v);
    }
    for (int t = tid; t < 128 * 136; t += 256) {
        int r = t / 136, c = t % 136;
        Bs[t] = (c < 128) ? tf32f(W_in[r * 128 + c]) : 0.f;
    }
    __syncthreads();
    float C[2][8][4] = {};
    gemm128<16, 132, 136>(As, Bs, C, tid);
    const int lane = tid & 31, warp = tid >> 5;
    const int wm = (warp >> 1) * 32, wn = (warp & 1) * 64;
    const int gid = lane >> 2, tig = lane & 3;
#pragma unroll
    for (int i = 0; i < 2; ++i)
#pragma unroll
        for (int h = 0; h < 2; ++h) {
            int row = r0 + wm + i * 16 + gid + h * 8;
            if (row < N_ATOMS)
#pragma unroll
                for (int j = 0; j < 8; ++j) {
                    int col = wn + j * 8 + 2 * tig;
                    float2 v = make_float2(C[i][j][h * 2], C[i][j][h * 2 + 1]);
                    *reinterpret_cast<float2*>(&g_x[(size_t)row * 128 + col]) = v;
                }
        }
}

// ---------------------------------------------------------------------------
// Phase A: persistent filter-network GEMMs; direct coalesced-ish STG of w.
// ---------------------------------------------------------------------------
__global__ __launch_bounds__(512, 1)
void k_pair(const float* __restrict__ f_ij, const float* __restrict__ cut,
            const float* __restrict__ W_f1, const float* __restrict__ b_f1,
            const float* __restrict__ W_f2, const float* __restrict__ b_f2,
            int tile_base, int tile_count) {
    extern __shared__ float smem[];
    const int tid = threadIdx.x;
    const int half = tid >> 8;
    const int htid = tid & 255;

    float* Bf2 = smem + OFF_BF2;
    float* Bf1 = smem + OFF_BF1;
    float* uni = smem + OFF_UNI0 + half * HALF_STRIDE;
    float* scut = uni + UNI_W;

    for (int t = tid; t < 128 * 128; t += 512) {
        int kk = t >> 7, n = t & 127;
        Bf2[bfrag_idx(kk, n, 16)] = tf32f(W_f2[kk * 128 + n]);
    }
    for (int t = tid; t < 24 * 128; t += 512) {
        int kk = t >> 7, n = t & 127;
        Bf1[bfrag_idx(kk, n, 3)] = (kk < 20) ? tf32f(W_f1[kk * 128 + n]) : 0.f;
    }
    if (tid < 128) smem[OFF_BB1 + tid] = b_f1[tid];
    else if (tid < 256) smem[OFF_BB2 + tid - 128] = b_f2[tid - 128];
    for (int t = htid; t < 3072; t += 256) uni[t] = 0.f;  // first-tile A1 pad
    __syncthreads();

    const float* b1s = smem + OFF_BB1;
    const float* b2s = smem + OFF_BB2;
    const int bar = 1 + half;
    const int lane = htid & 31, warp = htid >> 5;
    const int wm = (warp >> 1) * 32, wn = (warp & 1) * 64;
    const int gid = lane >> 2, tig = lane & 3;

    const int end = tile_base + tile_count;
    const int step = (int)gridDim.x * 2;
    int tile = tile_base + (int)blockIdx.x * 2 + half;
    if (tile >= end) return;

    const int prow = htid >> 1;
    const int pcol = (htid & 1) * 10;
    float pf[10];
    float pcut = 0.f;
    {
        const float* src = f_ij + (size_t)(tile * 128 + prow) * 20 + pcol;
#pragma unroll
        for (int q = 0; q < 10; ++q) pf[q] = tf32f(__ldg(src + q));
        if (htid < 128) pcut = __ldg(&cut[tile * 128 + htid]);
    }

    // S3 store mapping: m = bit-swapped tig; store float4 at A2-fragment slot
    const int mcol = ((tig & 1) << 1) | ((tig >> 1) & 1);
    float4* A2v = (float4*)uni + (warp >> 1) * 1024 + gid * 4 + mcol;

    for (; tile < end; tile += step) {
        const int p0 = tile * 128;

        // S1: prefetched f_ij -> fragment-major A1 + cutoff
#pragma unroll
        for (int q = 0; q < 10; ++q) uni[afrag_idx(prow, pcol + q, 3)] = pf[q];
        if (htid < 128) scut[htid] = pcut;
        barh(bar);

        // prefetch next tile
        int nt = tile + step;
        if (nt < end) {
            const float* src = f_ij + (size_t)(nt * 128 + prow) * 20 + pcol;
#pragma unroll
            for (int q = 0; q < 10; ++q) pf[q] = tf32f(__ldg(src + q));
            if (htid < 128) pcut = __ldg(&cut[nt * 128 + htid]);
        }

        // GEMM1 (K=24)
        float C[2][8][4] = {};
        gemmF<3>(uni, Bf1, C, htid);
        barh(bar);

        // S3: hidden = tf32(fssp(C+b1)); shuffle-pack into consumer float4s
#pragma unroll
        for (int i = 0; i < 2; ++i) {
#pragma unroll
            for (int j = 0; j < 8; ++j) {
                int col = wn + j * 8 + 2 * tig;
                float v0 = tf32f(fssp(C[i][j][0] + b1s[col]));
                float v1 = tf32f(fssp(C[i][j][1] + b1s[col + 1]));
                float v2 = tf32f(fssp(C[i][j][2] + b1s[col]));
                float v3 = tf32f(fssp(C[i][j][3] + b1s[col + 1]));
                float s0 = shfl_bfly((tig & 2) ? v0 : v1, 2);
                float s1 = shfl_bfly((tig & 2) ? v2 : v3, 2);
                float4 o = (tig & 2) ? make_float4(s0, s1, v1, v3)
                                     : make_float4(v0, v2, s0, s1);
                int k = (wn >> 3) + j;
                A2v[k * 64 + i * 32] = o;
            }
        }
        barh(bar);

        // GEMM2 (K=128)
        float C2[2][8][4] = {};
        gemmF<16>(uni, Bf2, C2, htid);

        // epilogue: w = (C2+b2)*cut  -> direct STG.64 to g_w
#pragma unroll
        for (int i = 0; i < 2; ++i) {
#pragma unroll
            for (int h = 0; h < 2; ++h) {
                int r = wm + i * 16 + gid + h * 8;
                float ct = scut[r];
                float* dst = g_w + (size_t)(p0 + r) * 128;
#pragma unroll
                for (int j = 0; j < 8; ++j) {
                    int col = wn + j * 8 + 2 * tig;
                    float2 v = make_float2((C2[i][j][h * 2] + b2s[col]) * ct,
                                           (C2[i][j][h * 2 + 1] + b2s[col + 1]) * ct);
                    *reinterpret_cast<float2*>(dst + col) = v;
                }
            }
        }
        barh(bar);  // A2/scut reads done before next S1 overwrite
    }
}

// ---------------------------------------------------------------------------
// Phase B: one warp per atom sums w[p] * x[j], unrolled x2 for MLP
// ---------------------------------------------------------------------------
__global__ __launch_bounds__(256, 2) void k_gather() {
    int atom = (blockIdx.x * 256 + threadIdx.x) >> 5;
    int lane = threadIdx.x & 31;
    if (atom >= N_ATOMS) return;
    int cnt = __ldg(&g_cnt[atom]);
    if (cnt > CAP) cnt = CAP;
    const int2* bucket = g_bucket + (size_t)atom * CAP;
    float4 acc = make_float4(0.f, 0.f, 0.f, 0.f);

    int t = 0;
    for (; t + 2 <= cnt; t += 2) {
        int2 e0 = __ldg(&bucket[t]);
        int2 e1 = __ldg(&bucket[t + 1]);
        float4 w0 = __ldg((const float4*)(g_w + (size_t)e0.x * 128) + lane);
        float4 x0 = __ldg((const float4*)(g_x + (size_t)e0.y * 128) + lane);
        float4 w1 = __ldg((const float4*)(g_w + (size_t)e1.x * 128) + lane);
        float4 x1 = __ldg((const float4*)(g_x + (size_t)e1.y * 128) + lane);
        acc.x += w0.x * x0.x; acc.y += w0.y * x0.y;
        acc.z += w0.z * x0.z; acc.w += w0.w * x0.w;
        acc.x += w1.x * x1.x; acc.y += w1.y * x1.y;
        acc.z += w1.z * x1.z; acc.w += w1.w * x1.w;
    }
    if (t < cnt) {
        int2 e = __ldg(&bucket[t]);
        float4 w = __ldg((const float4*)(g_w + (size_t)e.x * 128) + lane);
        float4 x = __ldg((const float4*)(g_x + (size_t)e.y * 128) + lane);
        acc.x += w.x * x.x; acc.y += w.y * x.y;
        acc.z += w.z * x.z; acc.w += w.w * x.w;
    }
    *((float4*)(g_acc + (size_t)atom * 128) + lane) = acc;
}

// ---------------------------------------------------------------------------
// Output MLP
// ---------------------------------------------------------------------------
__global__ __launch_bounds__(256, 1) void k_out(const float* __restrict__ W_o1,
                                                const float* __restrict__ b_o1,
                                                const float* __restrict__ W_o2,
                                                const float* __restrict__ b_o2,
                                                float* __restrict__ out) {
    extern __shared__ float smem[];
    float* As = smem;
    float* Bs = smem + 128 * 132;
    float* sbv = Bs + 128 * 136;
    const int tid = threadIdx.x;
    const int r0 = blockIdx.x * 128;
    for (int t = tid; t < 128 * 132; t += 256) {
        int r = t / 132, c = t % 132;
        float v = 0.f;
        if (c < 128 && (r0 + r) < N_ATOMS) v = g_acc[(size_t)(r0 + r) * 128 + c];
        As[t] = tf32f(v);
    }
    for (int t = tid; t < 128 * 136; t += 256) {
        int r = t / 136, c = t % 136;
        Bs[t] = (c < 128) ? tf32f(W_o1[r * 128 + c]) : 0.f;
    }
    if (tid < 128) sbv[tid] = b_o1[tid];
    __syncthreads();
    float C[2][8][4] = {};
    gemm128<16, 132, 136>(As, Bs, C, tid);
    __syncthreads();
    const int lane = tid & 31, warp = tid >> 5;
    const int wm = (warp >> 1) * 32, wn = (warp & 1) * 64;
    const int gid = lane >> 2, tig = lane & 3;
#pragma unroll
    for (int i = 0; i < 2; ++i) {
        int r = wm + i * 16 + gid;
#pragma unroll
        for (int j = 0; j < 8; ++j) {
            int col = wn + j * 8 + 2 * tig;
            As[r * 132 + col]           = tf32f(fssp(C[i][j][0] + sbv[col]));
            As[r * 132 + col + 1]       = tf32f(fssp(C[i][j][1] + sbv[col + 1]));
            As[(r + 8) * 132 + col]     = tf32f(fssp(C[i][j][2] + sbv[col]));
            As[(r + 8) * 132 + col + 1] = tf32f(fssp(C[i][j][3] + sbv[col + 1]));
        }
    }
    for (int t = tid; t < 128 * 136; t += 256) {
        int r = t / 136, c = t % 136;
        Bs[t] = (c < 128) ? tf32f(W_o2[r * 128 + c]) : 0.f;
    }
    if (tid < 128) sbv[tid] = b_o2[tid];
    __syncthreads();
    float C2[2][8][4] = {};
    gemm128<16, 132, 136>(As, Bs, C2, tid);
#pragma unroll
    for (int i = 0; i < 2; ++i)
#pragma unroll
        for (int h = 0; h < 2; ++h) {
            int row = r0 + wm + i * 16 + gid + h * 8;
            if (row < N_ATOMS)
#pragma unroll
                for (int j = 0; j < 8; ++j) {
                    int col = wn + j * 8 + 2 * tig;
                    float2 v = make_float2(C2[i][j][h * 2] + sbv[col],
                                           C2[i][j][h * 2 + 1] + sbv[col + 1]);
                    *reinterpret_cast<float2*>(&out[(size_t)row * 128 + col]) = v;
                }
        }
}

extern "C" void kernel_launch(void* const* d_in, const int* in_sizes, int n_in,
                              void* d_out, int out_size) {
    const float* emb  = (const float*)d_in[0];
    const int*   pidx = (const int*)d_in[1];
    const float* fij  = (const float*)d_in[2];
    const float* cut  = (const float*)d_in[3];
    const float* W_in = (const float*)d_in[4];
    const float* W_f1 = (const float*)d_in[5];
    const float* b_f1 = (const float*)d_in[6];
    const float* W_f2 = (const float*)d_in[7];
    const float* b_f2 = (const float*)d_in[8];
    const float* W_o1 = (const float*)d_in[9];
    const float* b_o1 = (const float*)d_in[10];
    const float* W_o2 = (const float*)d_in[11];
    const float* b_o2 = (const float*)d_in[12];
    float* out = (float*)d_out;

    const int smemPair = SMEM_PAIR_F * 4;  // 210944 B
    const int smemGemm = (128 * 132 + 128 * 136 + 128) * 4;

    cudaFuncSetAttribute(k_pair, cudaFuncAttributeMaxDynamicSharedMemorySize, smemPair);
    cudaFuncSetAttribute(k_proj, cudaFuncAttributeMaxDynamicSharedMemorySize, smemGemm);
    cudaFuncSetAttribute(k_out,  cudaFuncAttributeMaxDynamicSharedMemorySize, smemGemm);

    const int NT = N_PAIRS / 128;  // 12500
    k_czero<<<(N_ATOMS + 255) / 256, 256>>>();
    k_bucket<<<(N_PAIRS + 255) / 256, 256>>>(pidx);
    k_proj<<<(N_ATOMS + 127) / 128, 256, smemGemm>>>(emb, W_in);
    k_pair<<<148, 512, smemPair>>>(fij, cut, W_f1, b_f1, W_f2, b_f2, 0, NT);
    k_gather<<<(N_ATOMS * 32 + 255) / 256, 256>>>();
    k_out<<<(N_ATOMS + 127) / 128, 256, smemGemm>>>(W_o1, b_o1, W_o2, b_o2, out);
}